// round 2
// baseline (speedup 1.0000x reference)
#include <cuda_runtime.h>
#include <math.h>

#define SEQ 4096
#define EMB 1024
#define NH 8
#define HD 128

// Scratch (no allocations allowed): ~80MB of __device__ globals.
__device__ float g_qh[NH * SEQ * HD];
__device__ float g_kh[NH * SEQ * HD];
__device__ float g_vh[NH * SEQ * HD];
__device__ float g_z[SEQ * EMB];
__device__ float g_y[SEQ * EMB];

// ---------------------------------------------------------------------------
// GEMM: C[m,n] = sum_k X[m,k] * W[n,k] + bias[n]
// MODE 0/1/2: write to g_qh/g_kh/g_vh in [head][s][d] layout (n -> h=n>>7, d=n&127)
// MODE 3:     X = g_z (internal), adds resid (the original q input), writes g_y[m][n]
// BM=BN=128, BK=16, 256 threads, 8x8 per-thread register tile.
// ---------------------------------------------------------------------------
template <int MODE>
__global__ __launch_bounds__(256) void gemm_nt_kernel(
    const float* __restrict__ X, const float* __restrict__ W,
    const float* __restrict__ bias, const float* __restrict__ resid)
{
    __shared__ float As[16][128];
    __shared__ float Bs[16][128];

    const int m0 = blockIdx.y * 128;
    const int n0 = blockIdx.x * 128;
    const int tid = threadIdx.x;
    const int tx = tid & 15, ty = tid >> 4;

    const float* Xp = (MODE < 3) ? X : g_z;

    float acc[8][8];
#pragma unroll
    for (int i = 0; i < 8; i++)
#pragma unroll
        for (int j = 0; j < 8; j++) acc[i][j] = 0.f;

    const int lr = tid & 127;  // row within 128-row tile for loads
    const int lc = tid >> 7;   // 0..1

    for (int k0 = 0; k0 < EMB; k0 += 16) {
#pragma unroll
        for (int q = 0; q < 2; q++) {
            int k4 = lc * 2 + q;  // 0..3 (float4 column group)
            float4 av = *(const float4*)&Xp[(m0 + lr) * EMB + k0 + k4 * 4];
            As[k4 * 4 + 0][lr] = av.x; As[k4 * 4 + 1][lr] = av.y;
            As[k4 * 4 + 2][lr] = av.z; As[k4 * 4 + 3][lr] = av.w;
            float4 bv = *(const float4*)&W[(n0 + lr) * EMB + k0 + k4 * 4];
            Bs[k4 * 4 + 0][lr] = bv.x; Bs[k4 * 4 + 1][lr] = bv.y;
            Bs[k4 * 4 + 2][lr] = bv.z; Bs[k4 * 4 + 3][lr] = bv.w;
        }
        __syncthreads();
#pragma unroll
        for (int k = 0; k < 16; k++) {
            float4 a0 = *(const float4*)&As[k][ty * 8];
            float4 a1 = *(const float4*)&As[k][ty * 8 + 4];
            float4 b0 = *(const float4*)&Bs[k][tx * 8];
            float4 b1 = *(const float4*)&Bs[k][tx * 8 + 4];
            float a[8] = {a0.x, a0.y, a0.z, a0.w, a1.x, a1.y, a1.z, a1.w};
            float b[8] = {b0.x, b0.y, b0.z, b0.w, b1.x, b1.y, b1.z, b1.w};
#pragma unroll
            for (int i = 0; i < 8; i++)
#pragma unroll
                for (int j = 0; j < 8; j++) acc[i][j] += a[i] * b[j];
        }
        __syncthreads();
    }

#pragma unroll
    for (int i = 0; i < 8; i++) {
        int m = m0 + ty * 8 + i;
#pragma unroll
        for (int j = 0; j < 8; j++) {
            int n = n0 + tx * 8 + j;
            float v = acc[i][j] + bias[n];
            if (MODE == 3) {
                v += resid[m * EMB + n];
                g_y[m * EMB + n] = v;
            } else {
                int h = n >> 7, d = n & 127;
                float* outp = (MODE == 0) ? g_qh : (MODE == 1) ? g_kh : g_vh;
                outp[(h * SEQ + m) * HD + d] = v;
            }
        }
    }
}

// ---------------------------------------------------------------------------
// Flash-style attention per (head, 64-row q tile). 64-col kv tiles, DK=128.
// Online softmax; numerator accumulates p*group_prob*V, denominator plain p.
// Dynamic smem: Qs[128][68] Ks[128][68] Vs[64][128] Ps[64][68]  = 119808 B
// ---------------------------------------------------------------------------
#define ATTN_SMEM_FLOATS (2 * 128 * 68 + 64 * 128 + 64 * 68)
#define ATTN_SMEM_BYTES (ATTN_SMEM_FLOATS * 4)

__global__ __launch_bounds__(256) void attn_kernel(
    const int* __restrict__ mask, const float* __restrict__ gp)
{
    extern __shared__ float sm[];
    float (*Qs)[68]  = (float(*)[68])sm;
    float (*Ks)[68]  = (float(*)[68])(sm + 128 * 68);
    float (*Vs)[128] = (float(*)[128])(sm + 2 * 128 * 68);
    float (*Ps)[68]  = (float(*)[68])(sm + 2 * 128 * 68 + 64 * 128);

    const int h = blockIdx.y;
    const int s0 = blockIdx.x * 64;
    const int tid = threadIdx.x;
    const int tx = tid & 15, ty = tid >> 4;
    const float scale = 0.08838834764831845f;  // 1/sqrt(128)

    const float* Qg = g_qh + h * SEQ * HD;
    const float* Kg = g_kh + h * SEQ * HD;
    const float* Vg = g_vh + h * SEQ * HD;

    // Load Q tile transposed: Qs[d][i] = Q[s0+i][d]
    {
        int i = tid & 63;
        int d4b = tid >> 6;  // 0..3
#pragma unroll
        for (int r = 0; r < 8; r++) {
            int d4 = d4b + r * 4;  // 0..31
            float4 v = *(const float4*)&Qg[(s0 + i) * HD + d4 * 4];
            Qs[d4 * 4 + 0][i] = v.x; Qs[d4 * 4 + 1][i] = v.y;
            Qs[d4 * 4 + 2][i] = v.z; Qs[d4 * 4 + 3][i] = v.w;
        }
    }

    float o[4][8];
    float m_run[4], l_run[4];
#pragma unroll
    for (int i = 0; i < 4; i++) {
        m_run[i] = -INFINITY; l_run[i] = 0.f;
#pragma unroll
        for (int n = 0; n < 8; n++) o[i][n] = 0.f;
    }

    for (int t0 = 0; t0 < SEQ; t0 += 64) {
        // Load K transposed + V natural
        {
            int j = tid & 63;
            int d4b = tid >> 6;
#pragma unroll
            for (int r = 0; r < 8; r++) {
                int d4 = d4b + r * 4;
                float4 v = *(const float4*)&Kg[(t0 + j) * HD + d4 * 4];
                Ks[d4 * 4 + 0][j] = v.x; Ks[d4 * 4 + 1][j] = v.y;
                Ks[d4 * 4 + 2][j] = v.z; Ks[d4 * 4 + 3][j] = v.w;
            }
#pragma unroll
            for (int r = 0; r < 8; r++) {
                int idx = tid + 256 * r;  // 0..2047
                int vj = idx >> 5;        // 0..63
                int vd4 = idx & 31;       // 0..31
                *(float4*)&Vs[vj][vd4 * 4] =
                    *(const float4*)&Vg[(t0 + vj) * HD + vd4 * 4];
            }
        }
        __syncthreads();

        // S = Q K^T  (per-thread 4x4 of the 64x64 tile)
        float sacc[4][4];
#pragma unroll
        for (int i = 0; i < 4; i++)
#pragma unroll
            for (int j = 0; j < 4; j++) sacc[i][j] = 0.f;
#pragma unroll 4
        for (int d = 0; d < 128; d++) {
            float4 a = *(const float4*)&Qs[d][ty * 4];
            float4 b = *(const float4*)&Ks[d][tx * 4];
            float av[4] = {a.x, a.y, a.z, a.w};
            float bv[4] = {b.x, b.y, b.z, b.w};
#pragma unroll
            for (int i = 0; i < 4; i++)
#pragma unroll
                for (int j = 0; j < 4; j++) sacc[i][j] += av[i] * bv[j];
        }

        // scale + mask (reference: scale first, then mask -> -1e9)
#pragma unroll
        for (int i = 0; i < 4; i++) {
            int si = s0 + ty * 4 + i;
            const int* mrow = mask + si * SEQ + t0;
#pragma unroll
            for (int j = 0; j < 4; j++) {
                int tj = tx * 4 + j;
                float s = sacc[i][j] * scale;
                if (mrow[tj] == 0) s = -1e9f;
                sacc[i][j] = s;
            }
        }

        // row max across the 16 threads sharing each row (contiguous half-warp)
        float rmax[4];
#pragma unroll
        for (int i = 0; i < 4; i++) {
            float m = fmaxf(fmaxf(sacc[i][0], sacc[i][1]),
                            fmaxf(sacc[i][2], sacc[i][3]));
#pragma unroll
            for (int w = 1; w < 16; w <<= 1)
                m = fmaxf(m, __shfl_xor_sync(0xffffffffu, m, w));
            rmax[i] = m;
        }
#pragma unroll
        for (int i = 0; i < 4; i++) {
            float mn = fmaxf(m_run[i], rmax[i]);
            float alpha = __expf(m_run[i] - mn);
            m_run[i] = mn;
            l_run[i] *= alpha;
#pragma unroll
            for (int n = 0; n < 8; n++) o[i][n] *= alpha;
        }

        // p = exp(s - m); l += sum(p);  Ps (transposed) = p * group_prob
#pragma unroll
        for (int i = 0; i < 4; i++) {
            int si = s0 + ty * 4 + i;
            const float* grow = gp + si * SEQ + t0;
            float ls = 0.f;
#pragma unroll
            for (int j = 0; j < 4; j++) {
                int tj = tx * 4 + j;
                float e = __expf(sacc[i][j] - m_run[i]);
                ls += e;
                Ps[tj][ty * 4 + i] = e * grow[tj];
            }
#pragma unroll
            for (int w = 1; w < 16; w <<= 1)
                ls += __shfl_xor_sync(0xffffffffu, ls, w);
            l_run[i] += ls;
        }
        __syncthreads();

        // O += P' V  (per-thread 4x8 of the 64x128 tile)
#pragma unroll 4
        for (int j = 0; j < 64; j++) {
            float4 a = *(const float4*)&Ps[j][ty * 4];
            float4 b0 = *(const float4*)&Vs[j][tx * 8];
            float4 b1 = *(const float4*)&Vs[j][tx * 8 + 4];
            float av[4] = {a.x, a.y, a.z, a.w};
            float bv[8] = {b0.x, b0.y, b0.z, b0.w, b1.x, b1.y, b1.z, b1.w};
#pragma unroll
            for (int i = 0; i < 4; i++)
#pragma unroll
                for (int n = 0; n < 8; n++) o[i][n] += av[i] * bv[n];
        }
        __syncthreads();
    }

    // write z[s][h*128 + n] = O / l
#pragma unroll
    for (int i = 0; i < 4; i++) {
        int si = s0 + ty * 4 + i;
        float inv = 1.f / l_run[i];
#pragma unroll
        for (int n = 0; n < 8; n++)
            g_z[si * EMB + h * HD + tx * 8 + n] = o[i][n] * inv;
    }
}

// ---------------------------------------------------------------------------
// LayerNorm over last dim (1024). One block per row, 256 threads x 4 floats.
// ---------------------------------------------------------------------------
__global__ __launch_bounds__(256) void ln_kernel(
    const float* __restrict__ gam, const float* __restrict__ bet,
    float* __restrict__ out)
{
    __shared__ float red[2][8];
    int s = blockIdx.x;
    int tid = threadIdx.x;
    const float* row = g_y + s * EMB;

    float4 x = *(const float4*)&row[tid * 4];
    float sum = x.x + x.y + x.z + x.w;
    float sq = x.x * x.x + x.y * x.y + x.z * x.z + x.w * x.w;
#pragma unroll
    for (int w = 16; w; w >>= 1) {
        sum += __shfl_xor_sync(0xffffffffu, sum, w);
        sq  += __shfl_xor_sync(0xffffffffu, sq, w);
    }
    if ((tid & 31) == 0) { red[0][tid >> 5] = sum; red[1][tid >> 5] = sq; }
    __syncthreads();
    if (tid < 32) {
        float s1 = (tid < 8) ? red[0][tid] : 0.f;
        float s2 = (tid < 8) ? red[1][tid] : 0.f;
#pragma unroll
        for (int w = 4; w; w >>= 1) {
            s1 += __shfl_xor_sync(0xffffffffu, s1, w);
            s2 += __shfl_xor_sync(0xffffffffu, s2, w);
        }
        if (tid == 0) { red[0][0] = s1; red[1][0] = s2; }
    }
    __syncthreads();
    float mu = red[0][0] * (1.f / EMB);
    float var = red[1][0] * (1.f / EMB) - mu * mu;
    float inv = rsqrtf(var + 1e-5f);

    float4 gg = *(const float4*)&gam[tid * 4];
    float4 bb = *(const float4*)&bet[tid * 4];
    float4 o;
    o.x = (x.x - mu) * inv * gg.x + bb.x;
    o.y = (x.y - mu) * inv * gg.y + bb.y;
    o.z = (x.z - mu) * inv * gg.z + bb.z;
    o.w = (x.w - mu) * inv * gg.w + bb.w;
    *(float4*)&out[s * EMB + tid * 4] = o;
}

// ---------------------------------------------------------------------------
extern "C" void kernel_launch(void* const* d_in, const int* in_sizes, int n_in,
                              void* d_out, int out_size)
{
    const float* q    = (const float*)d_in[0];
    const float* k    = (const float*)d_in[1];
    const float* v    = (const float*)d_in[2];
    const int*   mask = (const int*)  d_in[3];
    const float* gp   = (const float*)d_in[4];
    const float* Wq   = (const float*)d_in[5];
    const float* bq   = (const float*)d_in[6];
    const float* Wk   = (const float*)d_in[7];
    const float* bk   = (const float*)d_in[8];
    const float* Wv   = (const float*)d_in[9];
    const float* bv   = (const float*)d_in[10];
    const float* Wo   = (const float*)d_in[11];
    const float* bo   = (const float*)d_in[12];
    const float* lng  = (const float*)d_in[13];
    const float* lnb  = (const float*)d_in[14];
    float* out = (float*)d_out;

    cudaFuncSetAttribute(attn_kernel, cudaFuncAttributeMaxDynamicSharedMemorySize,
                         ATTN_SMEM_BYTES);

    dim3 gproj(EMB / 128, SEQ / 128);  // (8, 32)
    gemm_nt_kernel<0><<<gproj, 256>>>(q, Wq, bq, nullptr);
    gemm_nt_kernel<1><<<gproj, 256>>>(k, Wk, bk, nullptr);
    gemm_nt_kernel<2><<<gproj, 256>>>(v, Wv, bv, nullptr);

    attn_kernel<<<dim3(SEQ / 64, NH), 256, ATTN_SMEM_BYTES>>>(mask, gp);

    gemm_nt_kernel<3><<<gproj, 256>>>(nullptr, Wo, bo, q);

    ln_kernel<<<SEQ, 256>>>(lng, lnb, out);
}

// round 3
// speedup vs baseline: 4.1844x; 4.1844x over previous
#include <cuda_runtime.h>
#include <cuda_bf16.h>
#include <math.h>

#define SEQ 4096
#define EMB 1024
#define NH 8
#define HD 128

// Scratch (no allocations allowed): __device__ globals.
__device__ __nv_bfloat16 g_qh[NH * SEQ * HD];
__device__ __nv_bfloat16 g_kh[NH * SEQ * HD];
__device__ __nv_bfloat16 g_vh[NH * SEQ * HD];
__device__ __nv_bfloat16 g_zb[SEQ * EMB];
__device__ float g_y[SEQ * EMB];

// ---------------------------------------------------------------------------
// MMA helpers (Ampere-style bf16 mma.sync, fp32 accumulate)
// ---------------------------------------------------------------------------
__device__ __forceinline__ unsigned smem_u32(const void* p) {
    return (unsigned)__cvta_generic_to_shared(p);
}

__device__ __forceinline__ void ldsm_x4(unsigned& r0, unsigned& r1,
                                        unsigned& r2, unsigned& r3, unsigned addr) {
    asm volatile("ldmatrix.sync.aligned.m8n8.x4.shared.b16 {%0,%1,%2,%3},[%4];"
                 : "=r"(r0), "=r"(r1), "=r"(r2), "=r"(r3) : "r"(addr));
}
__device__ __forceinline__ void ldsm_x4_t(unsigned& r0, unsigned& r1,
                                          unsigned& r2, unsigned& r3, unsigned addr) {
    asm volatile("ldmatrix.sync.aligned.m8n8.x4.trans.shared.b16 {%0,%1,%2,%3},[%4];"
                 : "=r"(r0), "=r"(r1), "=r"(r2), "=r"(r3) : "r"(addr));
}
__device__ __forceinline__ void mma_bf16(float* c, unsigned a0, unsigned a1,
                                         unsigned a2, unsigned a3,
                                         unsigned b0, unsigned b1) {
    asm volatile(
        "mma.sync.aligned.m16n8k16.row.col.f32.bf16.bf16.f32 "
        "{%0,%1,%2,%3},{%4,%5,%6,%7},{%8,%9},{%0,%1,%2,%3};"
        : "+f"(c[0]), "+f"(c[1]), "+f"(c[2]), "+f"(c[3])
        : "r"(a0), "r"(a1), "r"(a2), "r"(a3), "r"(b0), "r"(b1));
}
__device__ __forceinline__ unsigned pack2(float lo, float hi) {
    __nv_bfloat162 h;
    h.x = __float2bfloat16(lo);
    h.y = __float2bfloat16(hi);
    return *(unsigned*)&h;
}

// ---------------------------------------------------------------------------
// bf16 GEMM: C[m,n] = sum_k A[m,k]*W[n,k] + bias[n]   (W row-major [n][k])
// MODE 0/1/2: A = fp32 q/k/v -> write bf16 to g_qh/g_kh/g_vh [h][s][d]
// MODE 3:     A = bf16 g_zb  -> write fp32 g_y[m][n] = C + bias + resid
// BM=BN=128, BK=32, 256 threads = 8 warps (2 m x 4 n), warp tile 64x32.
// ---------------------------------------------------------------------------
#define GPAD 56  // bf16 row stride (32 + 24 pad): 112B, 16B-aligned, conflict-free ldsm

template <int MODE>
__global__ __launch_bounds__(256) void gemm_bf16_kernel(
    const float* __restrict__ Xf, const float* __restrict__ W,
    const float* __restrict__ bias, const float* __restrict__ resid)
{
    __shared__ __nv_bfloat16 Asm[128 * GPAD];
    __shared__ __nv_bfloat16 Bsm[128 * GPAD];

    const int m0 = blockIdx.y * 128, n0 = blockIdx.x * 128;
    const int tid = threadIdx.x, lane = tid & 31, w = tid >> 5;
    const int wm = (w >> 2) * 64, wn = (w & 3) * 32;

    float c[4][4][4];
#pragma unroll
    for (int i = 0; i < 4; i++)
#pragma unroll
        for (int j = 0; j < 4; j++)
#pragma unroll
            for (int e = 0; e < 4; e++) c[i][j][e] = 0.f;

    for (int k0 = 0; k0 < EMB; k0 += 32) {
        // ---- load A tile (128 x 32) ----
        if (MODE < 3) {
#pragma unroll
            for (int r = 0; r < 4; r++) {
                int idx = tid + 256 * r;
                int row = idx >> 3, c4 = idx & 7;
                float4 v = *(const float4*)&Xf[(m0 + row) * EMB + k0 + c4 * 4];
                __nv_bfloat16* p = &Asm[row * GPAD + c4 * 4];
                p[0] = __float2bfloat16(v.x); p[1] = __float2bfloat16(v.y);
                p[2] = __float2bfloat16(v.z); p[3] = __float2bfloat16(v.w);
            }
        } else {
#pragma unroll
            for (int r = 0; r < 2; r++) {
                int idx = tid + 256 * r;
                int row = idx >> 2, c8 = idx & 3;
                *(uint4*)&Asm[row * GPAD + c8 * 8] =
                    *(const uint4*)&g_zb[(m0 + row) * EMB + k0 + c8 * 8];
            }
        }
        // ---- load B tile (W: 128 n-rows x 32 k) ----
#pragma unroll
        for (int r = 0; r < 4; r++) {
            int idx = tid + 256 * r;
            int row = idx >> 3, c4 = idx & 7;
            float4 v = *(const float4*)&W[(n0 + row) * EMB + k0 + c4 * 4];
            __nv_bfloat16* p = &Bsm[row * GPAD + c4 * 4];
            p[0] = __float2bfloat16(v.x); p[1] = __float2bfloat16(v.y);
            p[2] = __float2bfloat16(v.z); p[3] = __float2bfloat16(v.w);
        }
        __syncthreads();

#pragma unroll
        for (int kk = 0; kk < 2; kk++) {
            unsigned a[4][4], b[4][2];
#pragma unroll
            for (int mf = 0; mf < 4; mf++) {
                int row = wm + mf * 16 + (lane & 15);
                int col = kk * 16 + (lane >> 4) * 8;
                ldsm_x4(a[mf][0], a[mf][1], a[mf][2], a[mf][3],
                        smem_u32(&Asm[row * GPAD + col]));
            }
#pragma unroll
            for (int nf2 = 0; nf2 < 2; nf2++) {
                int row = wn + nf2 * 16 + (lane & 7) + ((lane >> 4) << 3);
                int col = kk * 16 + ((lane >> 3) & 1) * 8;
                unsigned q0, q1, q2, q3;
                ldsm_x4(q0, q1, q2, q3, smem_u32(&Bsm[row * GPAD + col]));
                b[nf2 * 2][0] = q0; b[nf2 * 2][1] = q1;
                b[nf2 * 2 + 1][0] = q2; b[nf2 * 2 + 1][1] = q3;
            }
#pragma unroll
            for (int mf = 0; mf < 4; mf++)
#pragma unroll
                for (int nf = 0; nf < 4; nf++)
                    mma_bf16(c[mf][nf], a[mf][0], a[mf][1], a[mf][2], a[mf][3],
                             b[nf][0], b[nf][1]);
        }
        __syncthreads();
    }

    // ---- epilogue ----
    const int rl = lane >> 2, cb = (lane & 3) * 2;
#pragma unroll
    for (int mf = 0; mf < 4; mf++) {
        int row0 = m0 + wm + mf * 16 + rl;
#pragma unroll
        for (int nf = 0; nf < 4; nf++) {
            int n = n0 + wn + nf * 8 + cb;
            float b0 = bias[n], b1 = bias[n + 1];
            if (MODE == 3) {
                float2 r0v = *(const float2*)&resid[row0 * EMB + n];
                float2 r1v = *(const float2*)&resid[(row0 + 8) * EMB + n];
                float2 y0 = {c[mf][nf][0] + b0 + r0v.x, c[mf][nf][1] + b1 + r0v.y};
                float2 y1 = {c[mf][nf][2] + b0 + r1v.x, c[mf][nf][3] + b1 + r1v.y};
                *(float2*)&g_y[row0 * EMB + n] = y0;
                *(float2*)&g_y[(row0 + 8) * EMB + n] = y1;
            } else {
                int hh = n >> 7, d = n & 127;
                __nv_bfloat16* outp = (MODE == 0) ? g_qh : (MODE == 1) ? g_kh : g_vh;
                __nv_bfloat162 v0, v1;
                v0.x = __float2bfloat16(c[mf][nf][0] + b0);
                v0.y = __float2bfloat16(c[mf][nf][1] + b1);
                v1.x = __float2bfloat16(c[mf][nf][2] + b0);
                v1.y = __float2bfloat16(c[mf][nf][3] + b1);
                *(__nv_bfloat162*)&outp[(hh * SEQ + row0) * HD + d] = v0;
                *(__nv_bfloat162*)&outp[(hh * SEQ + row0 + 8) * HD + d] = v1;
            }
        }
    }
}

// ---------------------------------------------------------------------------
// Flash attention, bf16 MMA. Block = 64 q-rows x 1 head, 4 warps (16 rows ea).
// S = Q K^T (k=128), online softmax, P' = p*group_prob, O += P' V, l += sum p.
// ---------------------------------------------------------------------------
#define APAD 136  // bf16 row stride (128+8): 272B, 16B-aligned, conflict-free ldsm
#define ATTN_SMEM_BYTES (3 * 64 * APAD * 2)

__global__ __launch_bounds__(128) void attn_bf16_kernel(
    const int* __restrict__ mask, const float* __restrict__ gp)
{
    extern __shared__ __nv_bfloat16 sm_[];
    __nv_bfloat16* Qs = sm_;
    __nv_bfloat16* Ks = sm_ + 64 * APAD;
    __nv_bfloat16* Vs = sm_ + 2 * 64 * APAD;

    const int h = blockIdx.y, s0 = blockIdx.x * 64;
    const int tid = threadIdx.x, lane = tid & 31, w = tid >> 5;
    const float SCALE = 0.08838834764831845f;  // 1/sqrt(128)

    const __nv_bfloat16* Qg = g_qh + h * SEQ * HD;
    const __nv_bfloat16* Kg = g_kh + h * SEQ * HD;
    const __nv_bfloat16* Vg = g_vh + h * SEQ * HD;

    // load Q tile (64 x 128)
#pragma unroll
    for (int r = 0; r < 8; r++) {
        int idx = tid + 128 * r;
        int row = idx >> 4, c8 = idx & 15;
        *(uint4*)&Qs[row * APAD + c8 * 8] =
            *(const uint4*)&Qg[(s0 + row) * HD + c8 * 8];
    }
    __syncthreads();

    // preload Q fragments (8 k-steps x 4 regs)
    unsigned aq[8][4];
#pragma unroll
    for (int kf = 0; kf < 8; kf++) {
        int row = w * 16 + (lane & 15);
        int col = kf * 16 + (lane >> 4) * 8;
        ldsm_x4(aq[kf][0], aq[kf][1], aq[kf][2], aq[kf][3],
                smem_u32(&Qs[row * APAD + col]));
    }

    float o[16][4];
    float m_run[2] = {-INFINITY, -INFINITY};
    float l_run[2] = {0.f, 0.f};
#pragma unroll
    for (int nf = 0; nf < 16; nf++)
#pragma unroll
        for (int e = 0; e < 4; e++) o[nf][e] = 0.f;

    const int r0 = s0 + w * 16 + (lane >> 2);
    const int tcol = (lane & 3) * 2;

    for (int t0 = 0; t0 < SEQ; t0 += 64) {
        __syncthreads();  // previous tile's consumers done before overwrite
#pragma unroll
        for (int r = 0; r < 8; r++) {
            int idx = tid + 128 * r;
            int row = idx >> 4, c8 = idx & 15;
            *(uint4*)&Ks[row * APAD + c8 * 8] =
                *(const uint4*)&Kg[(t0 + row) * HD + c8 * 8];
            *(uint4*)&Vs[row * APAD + c8 * 8] =
                *(const uint4*)&Vg[(t0 + row) * HD + c8 * 8];
        }
        __syncthreads();

        // ---- S = Q K^T : 8 n-frags (t), 8 k-steps (d) ----
        float s[8][4];
#pragma unroll
        for (int nf = 0; nf < 8; nf++)
#pragma unroll
            for (int e = 0; e < 4; e++) s[nf][e] = 0.f;

#pragma unroll
        for (int kf = 0; kf < 8; kf++) {
            unsigned b[8][2];
#pragma unroll
            for (int nf2 = 0; nf2 < 4; nf2++) {
                int row = nf2 * 16 + (lane & 7) + ((lane >> 4) << 3);
                int col = kf * 16 + ((lane >> 3) & 1) * 8;
                unsigned q0, q1, q2, q3;
                ldsm_x4(q0, q1, q2, q3, smem_u32(&Ks[row * APAD + col]));
                b[nf2 * 2][0] = q0; b[nf2 * 2][1] = q1;
                b[nf2 * 2 + 1][0] = q2; b[nf2 * 2 + 1][1] = q3;
            }
#pragma unroll
            for (int nf = 0; nf < 8; nf++)
                mma_bf16(s[nf], aq[kf][0], aq[kf][1], aq[kf][2], aq[kf][3],
                         b[nf][0], b[nf][1]);
        }

        // ---- scale + mask + online softmax (two rows: r0, r0+8) ----
#pragma unroll
        for (int rr = 0; rr < 2; rr++) {
            int srow = r0 + rr * 8;
            float mx = -1e30f;
#pragma unroll
            for (int nf = 0; nf < 8; nf++) {
                int t = t0 + nf * 8 + tcol;
                int2 mk = *(const int2*)&mask[srow * SEQ + t];
                float e0 = s[nf][rr * 2] * SCALE;
                float e1 = s[nf][rr * 2 + 1] * SCALE;
                if (mk.x == 0) e0 = -1e9f;
                if (mk.y == 0) e1 = -1e9f;
                s[nf][rr * 2] = e0;
                s[nf][rr * 2 + 1] = e1;
                mx = fmaxf(mx, fmaxf(e0, e1));
            }
            mx = fmaxf(mx, __shfl_xor_sync(0xffffffffu, mx, 1));
            mx = fmaxf(mx, __shfl_xor_sync(0xffffffffu, mx, 2));
            float mn = fmaxf(m_run[rr], mx);
            float alpha = __expf(m_run[rr] - mn);
            m_run[rr] = mn;
            l_run[rr] *= alpha;
#pragma unroll
            for (int nf = 0; nf < 16; nf++) {
                o[nf][rr * 2] *= alpha;
                o[nf][rr * 2 + 1] *= alpha;
            }
            float ls = 0.f;
#pragma unroll
            for (int nf = 0; nf < 8; nf++) {
                float p0 = __expf(s[nf][rr * 2] - mn);
                float p1 = __expf(s[nf][rr * 2 + 1] - mn);
                ls += p0 + p1;
                float2 g2 = *(const float2*)&gp[srow * SEQ + t0 + nf * 8 + tcol];
                s[nf][rr * 2] = p0 * g2.x;       // P' = p * group_prob
                s[nf][rr * 2 + 1] = p1 * g2.y;
            }
            ls += __shfl_xor_sync(0xffffffffu, ls, 1);
            ls += __shfl_xor_sync(0xffffffffu, ls, 2);
            l_run[rr] += ls;
        }

        // ---- O += P' V : reuse S fragments as A fragments ----
#pragma unroll
        for (int kf = 0; kf < 4; kf++) {
            unsigned a0 = pack2(s[2 * kf][0], s[2 * kf][1]);
            unsigned a1 = pack2(s[2 * kf][2], s[2 * kf][3]);
            unsigned a2 = pack2(s[2 * kf + 1][0], s[2 * kf + 1][1]);
            unsigned a3 = pack2(s[2 * kf + 1][2], s[2 * kf + 1][3]);
#pragma unroll
            for (int df2 = 0; df2 < 8; df2++) {
                int row = kf * 16 + (lane & 7) + ((lane >> 3) & 1) * 8;
                int col = df2 * 16 + (lane >> 4) * 8;
                unsigned v0, v1, v2, v3;
                ldsm_x4_t(v0, v1, v2, v3, smem_u32(&Vs[row * APAD + col]));
                mma_bf16(o[2 * df2], a0, a1, a2, a3, v0, v1);
                mma_bf16(o[2 * df2 + 1], a0, a1, a2, a3, v2, v3);
            }
        }
    }

    // ---- write z (bf16) ----
    float inv0 = 1.f / l_run[0], inv1 = 1.f / l_run[1];
#pragma unroll
    for (int nf = 0; nf < 16; nf++) {
        int d = nf * 8 + tcol;
        __nv_bfloat162 p0, p1;
        p0.x = __float2bfloat16(o[nf][0] * inv0);
        p0.y = __float2bfloat16(o[nf][1] * inv0);
        p1.x = __float2bfloat16(o[nf][2] * inv1);
        p1.y = __float2bfloat16(o[nf][3] * inv1);
        *(__nv_bfloat162*)&g_zb[r0 * EMB + h * HD + d] = p0;
        *(__nv_bfloat162*)&g_zb[(r0 + 8) * EMB + h * HD + d] = p1;
    }
}

// ---------------------------------------------------------------------------
// LayerNorm over last dim (1024). One block per row.
// ---------------------------------------------------------------------------
__global__ __launch_bounds__(256) void ln_kernel(
    const float* __restrict__ gam, const float* __restrict__ bet,
    float* __restrict__ out)
{
    __shared__ float red[2][8];
    int s = blockIdx.x;
    int tid = threadIdx.x;
    const float* row = g_y + s * EMB;

    float4 x = *(const float4*)&row[tid * 4];
    float sum = x.x + x.y + x.z + x.w;
    float sq = x.x * x.x + x.y * x.y + x.z * x.z + x.w * x.w;
#pragma unroll
    for (int w = 16; w; w >>= 1) {
        sum += __shfl_xor_sync(0xffffffffu, sum, w);
        sq  += __shfl_xor_sync(0xffffffffu, sq, w);
    }
    if ((tid & 31) == 0) { red[0][tid >> 5] = sum; red[1][tid >> 5] = sq; }
    __syncthreads();
    if (tid < 32) {
        float s1 = (tid < 8) ? red[0][tid] : 0.f;
        float s2 = (tid < 8) ? red[1][tid] : 0.f;
#pragma unroll
        for (int w = 4; w; w >>= 1) {
            s1 += __shfl_xor_sync(0xffffffffu, s1, w);
            s2 += __shfl_xor_sync(0xffffffffu, s2, w);
        }
        if (tid == 0) { red[0][0] = s1; red[1][0] = s2; }
    }
    __syncthreads();
    float mu = red[0][0] * (1.f / EMB);
    float var = red[1][0] * (1.f / EMB) - mu * mu;
    float inv = rsqrtf(var + 1e-5f);

    float4 gg = *(const float4*)&gam[tid * 4];
    float4 bb = *(const float4*)&bet[tid * 4];
    float4 o;
    o.x = (x.x - mu) * inv * gg.x + bb.x;
    o.y = (x.y - mu) * inv * gg.y + bb.y;
    o.z = (x.z - mu) * inv * gg.z + bb.z;
    o.w = (x.w - mu) * inv * gg.w + bb.w;
    *(float4*)&out[s * EMB + tid * 4] = o;
}

// ---------------------------------------------------------------------------
extern "C" void kernel_launch(void* const* d_in, const int* in_sizes, int n_in,
                              void* d_out, int out_size)
{
    const float* q    = (const float*)d_in[0];
    const float* k    = (const float*)d_in[1];
    const float* v    = (const float*)d_in[2];
    const int*   mask = (const int*)  d_in[3];
    const float* gp   = (const float*)d_in[4];
    const float* Wq   = (const float*)d_in[5];
    const float* bq   = (const float*)d_in[6];
    const float* Wk   = (const float*)d_in[7];
    const float* bk   = (const float*)d_in[8];
    const float* Wv   = (const float*)d_in[9];
    const float* bv   = (const float*)d_in[10];
    const float* Wo   = (const float*)d_in[11];
    const float* bo   = (const float*)d_in[12];
    const float* lng  = (const float*)d_in[13];
    const float* lnb  = (const float*)d_in[14];
    float* out = (float*)d_out;

    cudaFuncSetAttribute(attn_bf16_kernel,
                         cudaFuncAttributeMaxDynamicSharedMemorySize,
                         ATTN_SMEM_BYTES);

    dim3 gproj(EMB / 128, SEQ / 128);  // (8, 32)
    gemm_bf16_kernel<0><<<gproj, 256>>>(q, Wq, bq, nullptr);
    gemm_bf16_kernel<1><<<gproj, 256>>>(k, Wk, bk, nullptr);
    gemm_bf16_kernel<2><<<gproj, 256>>>(v, Wv, bv, nullptr);

    attn_bf16_kernel<<<dim3(SEQ / 64, NH), 128, ATTN_SMEM_BYTES>>>(mask, gp);

    gemm_bf16_kernel<3><<<gproj, 256>>>(nullptr, Wo, bo, q);

    ln_kernel<<<SEQ, 256>>>(lng, lnb, out);
}

// round 4
// speedup vs baseline: 7.6848x; 1.8365x over previous
#include <cuda_runtime.h>
#include <cuda_bf16.h>
#include <math.h>

#define SEQ 4096
#define EMB 1024
#define NH 8
#define HD 128

// Scratch (no allocations allowed): __device__ globals.
__device__ __nv_bfloat16 g_qh[NH * SEQ * HD];
__device__ __nv_bfloat16 g_kh[NH * SEQ * HD];
__device__ __nv_bfloat16 g_vh[NH * SEQ * HD];
__device__ __nv_bfloat16 g_zb[SEQ * EMB];
__device__ __nv_bfloat16 g_gpm[SEQ * SEQ];  // mask? gp : -1  (bf16)
__device__ float g_y[SEQ * EMB];

// ---------------------------------------------------------------------------
// helpers
// ---------------------------------------------------------------------------
__device__ __forceinline__ unsigned smem_u32(const void* p) {
    return (unsigned)__cvta_generic_to_shared(p);
}
__device__ __forceinline__ void cp16(void* dst, const void* src) {
    asm volatile("cp.async.cg.shared.global [%0],[%1],16;"
                 :: "r"(smem_u32(dst)), "l"(src));
}
__device__ __forceinline__ void cp_commit() {
    asm volatile("cp.async.commit_group;");
}
template <int N>
__device__ __forceinline__ void cp_wait() {
    asm volatile("cp.async.wait_group %0;" :: "n"(N));
}
__device__ __forceinline__ void ldsm_x4(unsigned& r0, unsigned& r1,
                                        unsigned& r2, unsigned& r3, unsigned addr) {
    asm volatile("ldmatrix.sync.aligned.m8n8.x4.shared.b16 {%0,%1,%2,%3},[%4];"
                 : "=r"(r0), "=r"(r1), "=r"(r2), "=r"(r3) : "r"(addr));
}
__device__ __forceinline__ void ldsm_x4_t(unsigned& r0, unsigned& r1,
                                          unsigned& r2, unsigned& r3, unsigned addr) {
    asm volatile("ldmatrix.sync.aligned.m8n8.x4.trans.shared.b16 {%0,%1,%2,%3},[%4];"
                 : "=r"(r0), "=r"(r1), "=r"(r2), "=r"(r3) : "r"(addr));
}
__device__ __forceinline__ void mma_bf16(float* c, unsigned a0, unsigned a1,
                                         unsigned a2, unsigned a3,
                                         unsigned b0, unsigned b1) {
    asm volatile(
        "mma.sync.aligned.m16n8k16.row.col.f32.bf16.bf16.f32 "
        "{%0,%1,%2,%3},{%4,%5,%6,%7},{%8,%9},{%0,%1,%2,%3};"
        : "+f"(c[0]), "+f"(c[1]), "+f"(c[2]), "+f"(c[3])
        : "r"(a0), "r"(a1), "r"(a2), "r"(a3), "r"(b0), "r"(b1));
}
__device__ __forceinline__ unsigned pack2(float lo, float hi) {
    __nv_bfloat162 h;
    h.x = __float2bfloat16(lo);
    h.y = __float2bfloat16(hi);
    return *(unsigned*)&h;
}

// ---------------------------------------------------------------------------
// prep: gpm[s][t] = mask ? gp : -1   (bf16)
// ---------------------------------------------------------------------------
__global__ __launch_bounds__(256) void prep_gpm_kernel(
    const int* __restrict__ mask, const float* __restrict__ gp)
{
    int idx = (blockIdx.x * 256 + threadIdx.x) * 4;
    int4 m = *(const int4*)&mask[idx];
    float4 g = *(const float4*)&gp[idx];
    __nv_bfloat16 o[4];
    o[0] = __float2bfloat16(m.x ? g.x : -1.f);
    o[1] = __float2bfloat16(m.y ? g.y : -1.f);
    o[2] = __float2bfloat16(m.z ? g.z : -1.f);
    o[3] = __float2bfloat16(m.w ? g.w : -1.f);
    *(uint2*)&g_gpm[idx] = *(uint2*)o;
}

// ---------------------------------------------------------------------------
// bf16 GEMM: C[m,n] = sum_k A[m,k]*W[n,k] + bias[n]   (W row-major [n][k])
// QKV kernel: blockIdx.z selects (q,Wq,bq)->g_qh etc, bf16 out [h][s][d]
// OUT kernel: A = bf16 g_zb -> fp32 g_y = C + bias + resid
// BM=BN=128, BK=32, 256 threads = 8 warps (2m x 4n), warp tile 64x32.
// ---------------------------------------------------------------------------
#define GPAD 56

__device__ __forceinline__ void gemm_core(
    const float* Xf, const __nv_bfloat16* Xb, const float* W,
    int m0, int n0, float c[4][4][4],
    __nv_bfloat16* Asm, __nv_bfloat16* Bsm)
{
    const int tid = threadIdx.x, lane = tid & 31, w = tid >> 5;
    const int wm = (w >> 2) * 64, wn = (w & 3) * 32;

    for (int k0 = 0; k0 < EMB; k0 += 32) {
        if (Xf) {
#pragma unroll
            for (int r = 0; r < 4; r++) {
                int idx = tid + 256 * r;
                int row = idx >> 3, c4 = idx & 7;
                float4 v = *(const float4*)&Xf[(m0 + row) * EMB + k0 + c4 * 4];
                __nv_bfloat16* p = &Asm[row * GPAD + c4 * 4];
                p[0] = __float2bfloat16(v.x); p[1] = __float2bfloat16(v.y);
                p[2] = __float2bfloat16(v.z); p[3] = __float2bfloat16(v.w);
            }
        } else {
#pragma unroll
            for (int r = 0; r < 2; r++) {
                int idx = tid + 256 * r;
                int row = idx >> 2, c8 = idx & 3;
                *(uint4*)&Asm[row * GPAD + c8 * 8] =
                    *(const uint4*)&Xb[(m0 + row) * EMB + k0 + c8 * 8];
            }
        }
#pragma unroll
        for (int r = 0; r < 4; r++) {
            int idx = tid + 256 * r;
            int row = idx >> 3, c4 = idx & 7;
            float4 v = *(const float4*)&W[(n0 + row) * EMB + k0 + c4 * 4];
            __nv_bfloat16* p = &Bsm[row * GPAD + c4 * 4];
            p[0] = __float2bfloat16(v.x); p[1] = __float2bfloat16(v.y);
            p[2] = __float2bfloat16(v.z); p[3] = __float2bfloat16(v.w);
        }
        __syncthreads();
#pragma unroll
        for (int kk = 0; kk < 2; kk++) {
            unsigned a[4][4], b[4][2];
#pragma unroll
            for (int mf = 0; mf < 4; mf++) {
                int row = wm + mf * 16 + (lane & 15);
                int col = kk * 16 + (lane >> 4) * 8;
                ldsm_x4(a[mf][0], a[mf][1], a[mf][2], a[mf][3],
                        smem_u32(&Asm[row * GPAD + col]));
            }
#pragma unroll
            for (int nf2 = 0; nf2 < 2; nf2++) {
                int row = wn + nf2 * 16 + (lane & 7) + ((lane >> 4) << 3);
                int col = kk * 16 + ((lane >> 3) & 1) * 8;
                unsigned q0, q1, q2, q3;
                ldsm_x4(q0, q1, q2, q3, smem_u32(&Bsm[row * GPAD + col]));
                b[nf2 * 2][0] = q0; b[nf2 * 2][1] = q1;
                b[nf2 * 2 + 1][0] = q2; b[nf2 * 2 + 1][1] = q3;
            }
#pragma unroll
            for (int mf = 0; mf < 4; mf++)
#pragma unroll
                for (int nf = 0; nf < 4; nf++)
                    mma_bf16(c[mf][nf], a[mf][0], a[mf][1], a[mf][2], a[mf][3],
                             b[nf][0], b[nf][1]);
        }
        __syncthreads();
    }
}

__global__ __launch_bounds__(256) void gemm_qkv_kernel(
    const float* __restrict__ q, const float* __restrict__ k,
    const float* __restrict__ v,
    const float* __restrict__ Wq, const float* __restrict__ Wk,
    const float* __restrict__ Wv,
    const float* __restrict__ bq, const float* __restrict__ bk,
    const float* __restrict__ bv)
{
    __shared__ __nv_bfloat16 Asm[128 * GPAD];
    __shared__ __nv_bfloat16 Bsm[128 * GPAD];
    const int z = blockIdx.z;
    const float* X = (z == 0) ? q : (z == 1) ? k : v;
    const float* W = (z == 0) ? Wq : (z == 1) ? Wk : Wv;
    const float* bias = (z == 0) ? bq : (z == 1) ? bk : bv;
    __nv_bfloat16* outp = (z == 0) ? g_qh : (z == 1) ? g_kh : g_vh;

    const int m0 = blockIdx.y * 128, n0 = blockIdx.x * 128;
    const int tid = threadIdx.x, lane = tid & 31, w = tid >> 5;
    const int wm = (w >> 2) * 64, wn = (w & 3) * 32;

    float c[4][4][4];
#pragma unroll
    for (int i = 0; i < 4; i++)
#pragma unroll
        for (int j = 0; j < 4; j++)
#pragma unroll
            for (int e = 0; e < 4; e++) c[i][j][e] = 0.f;

    gemm_core(X, nullptr, W, m0, n0, c, Asm, Bsm);

    const int rl = lane >> 2, cb = (lane & 3) * 2;
#pragma unroll
    for (int mf = 0; mf < 4; mf++) {
        int row0 = m0 + wm + mf * 16 + rl;
#pragma unroll
        for (int nf = 0; nf < 4; nf++) {
            int n = n0 + wn + nf * 8 + cb;
            float b0 = bias[n], b1 = bias[n + 1];
            int hh = n >> 7, d = n & 127;
            __nv_bfloat162 v0, v1;
            v0.x = __float2bfloat16(c[mf][nf][0] + b0);
            v0.y = __float2bfloat16(c[mf][nf][1] + b1);
            v1.x = __float2bfloat16(c[mf][nf][2] + b0);
            v1.y = __float2bfloat16(c[mf][nf][3] + b1);
            *(__nv_bfloat162*)&outp[(hh * SEQ + row0) * HD + d] = v0;
            *(__nv_bfloat162*)&outp[(hh * SEQ + row0 + 8) * HD + d] = v1;
        }
    }
}

__global__ __launch_bounds__(256) void gemm_out_kernel(
    const float* __restrict__ Wo, const float* __restrict__ bo,
    const float* __restrict__ resid)
{
    __shared__ __nv_bfloat16 Asm[128 * GPAD];
    __shared__ __nv_bfloat16 Bsm[128 * GPAD];
    const int m0 = blockIdx.y * 128, n0 = blockIdx.x * 128;
    const int tid = threadIdx.x, lane = tid & 31, w = tid >> 5;
    const int wm = (w >> 2) * 64, wn = (w & 3) * 32;

    float c[4][4][4];
#pragma unroll
    for (int i = 0; i < 4; i++)
#pragma unroll
        for (int j = 0; j < 4; j++)
#pragma unroll
            for (int e = 0; e < 4; e++) c[i][j][e] = 0.f;

    gemm_core(nullptr, g_zb, Wo, m0, n0, c, Asm, Bsm);

    const int rl = lane >> 2, cb = (lane & 3) * 2;
#pragma unroll
    for (int mf = 0; mf < 4; mf++) {
        int row0 = m0 + wm + mf * 16 + rl;
#pragma unroll
        for (int nf = 0; nf < 4; nf++) {
            int n = n0 + wn + nf * 8 + cb;
            float b0 = bo[n], b1 = bo[n + 1];
            float2 r0v = *(const float2*)&resid[row0 * EMB + n];
            float2 r1v = *(const float2*)&resid[(row0 + 8) * EMB + n];
            float2 y0 = {c[mf][nf][0] + b0 + r0v.x, c[mf][nf][1] + b1 + r0v.y};
            float2 y1 = {c[mf][nf][2] + b0 + r1v.x, c[mf][nf][3] + b1 + r1v.y};
            *(float2*)&g_y[row0 * EMB + n] = y0;
            *(float2*)&g_y[(row0 + 8) * EMB + n] = y1;
        }
    }
}

// ---------------------------------------------------------------------------
// Flash attention, bf16 MMA, fixed-max softmax, cp.async double buffering.
// Block = 64 q-rows x 1 head, 128 threads (4 warps, 16 rows each).
// p = exp2(s_raw*SC2 - M2); masked (gpm<0) -> 0; l += p; P' = p*gpm.
// ---------------------------------------------------------------------------
#define APAD 136          // K/V/Q bf16 row stride
#define GPMPAD 72         // gpm bf16 row stride
#define Q_ELEMS (64 * APAD)
#define G_ELEMS (64 * GPMPAD)
// layout (bf16 elems): Q | K0 | K1 | V0 | V1 | G0 | G1
#define OFF_K(st) (Q_ELEMS + (st) * Q_ELEMS)
#define OFF_V(st) (3 * Q_ELEMS + (st) * Q_ELEMS)
#define OFF_G(st) (5 * Q_ELEMS + (st) * G_ELEMS)
#define ATTN_SMEM_BYTES ((5 * Q_ELEMS + 2 * G_ELEMS) * 2)

__global__ __launch_bounds__(128) void attn_bf16_kernel()
{
    extern __shared__ __nv_bfloat16 sm_[];
    const int h = blockIdx.y, s0 = blockIdx.x * 64;
    const int tid = threadIdx.x, lane = tid & 31, w = tid >> 5;
    const float SC2 = 0.12751744f;   // log2(e)/sqrt(128)
    const float M2 = 11.541560f;     // 8*log2(e)

    const __nv_bfloat16* Qg = g_qh + h * SEQ * HD;
    const __nv_bfloat16* Kg = g_kh + h * SEQ * HD;
    const __nv_bfloat16* Vg = g_vh + h * SEQ * HD;

    // ---- group 0: Q tile ----
#pragma unroll
    for (int r = 0; r < 8; r++) {
        int idx = tid + 128 * r;
        int row = idx >> 4, ch = idx & 15;
        cp16(&sm_[row * APAD + ch * 8], &Qg[(s0 + row) * HD + ch * 8]);
    }
    cp_commit();

    // ---- group 1: tile 0 of K/V/gpm ----
    {
        const int t0 = 0, st = 0;
#pragma unroll
        for (int r = 0; r < 8; r++) {
            int idx = tid + 128 * r;
            int row = idx >> 4, ch = idx & 15;
            cp16(&sm_[OFF_K(st) + row * APAD + ch * 8], &Kg[(t0 + row) * HD + ch * 8]);
            cp16(&sm_[OFF_V(st) + row * APAD + ch * 8], &Vg[(t0 + row) * HD + ch * 8]);
        }
#pragma unroll
        for (int r = 0; r < 4; r++) {
            int idx = tid + 128 * r;
            int row = idx >> 3, ch = idx & 7;
            cp16(&sm_[OFF_G(st) + row * GPMPAD + ch * 8],
                 &g_gpm[(s0 + row) * SEQ + t0 + ch * 8]);
        }
        cp_commit();
    }

    cp_wait<1>();   // Q done
    __syncthreads();

    // preload Q fragments (8 k-steps x 4 regs)
    unsigned aq[8][4];
#pragma unroll
    for (int kf = 0; kf < 8; kf++) {
        int row = w * 16 + (lane & 15);
        int col = kf * 16 + (lane >> 4) * 8;
        ldsm_x4(aq[kf][0], aq[kf][1], aq[kf][2], aq[kf][3],
                smem_u32(&sm_[row * APAD + col]));
    }

    float o[16][4];
    float l_run[2] = {0.f, 0.f};
#pragma unroll
    for (int nf = 0; nf < 16; nf++)
#pragma unroll
        for (int e = 0; e < 4; e++) o[nf][e] = 0.f;

    const int rloc = w * 16 + (lane >> 2);        // local q row (rr=0)
    const int r0 = s0 + rloc;
    const int tcol = (lane & 3) * 2;

    for (int i = 0; i < SEQ / 64; i++) {
        // prefetch next tile
        if (i + 1 < SEQ / 64) {
            const int t1 = (i + 1) * 64, st = (i + 1) & 1;
#pragma unroll
            for (int r = 0; r < 8; r++) {
                int idx = tid + 128 * r;
                int row = idx >> 4, ch = idx & 15;
                cp16(&sm_[OFF_K(st) + row * APAD + ch * 8], &Kg[(t1 + row) * HD + ch * 8]);
                cp16(&sm_[OFF_V(st) + row * APAD + ch * 8], &Vg[(t1 + row) * HD + ch * 8]);
            }
#pragma unroll
            for (int r = 0; r < 4; r++) {
                int idx = tid + 128 * r;
                int row = idx >> 3, ch = idx & 7;
                cp16(&sm_[OFF_G(st) + row * GPMPAD + ch * 8],
                     &g_gpm[(s0 + row) * SEQ + t1 + ch * 8]);
            }
            cp_commit();
            cp_wait<1>();
        } else {
            cp_wait<0>();
        }
        __syncthreads();

        const int st = i & 1;
        const __nv_bfloat16* Ks = sm_ + OFF_K(st);
        const __nv_bfloat16* Vs = sm_ + OFF_V(st);
        const __nv_bfloat16* Gs = sm_ + OFF_G(st);

        // ---- S = Q K^T ----
        float s[8][4];
#pragma unroll
        for (int nf = 0; nf < 8; nf++)
#pragma unroll
            for (int e = 0; e < 4; e++) s[nf][e] = 0.f;

#pragma unroll
        for (int kf = 0; kf < 8; kf++) {
            unsigned b[8][2];
#pragma unroll
            for (int nf2 = 0; nf2 < 4; nf2++) {
                int row = nf2 * 16 + (lane & 7) + ((lane >> 4) << 3);
                int col = kf * 16 + ((lane >> 3) & 1) * 8;
                unsigned q0, q1, q2, q3;
                ldsm_x4(q0, q1, q2, q3, smem_u32(&Ks[row * APAD + col]));
                b[nf2 * 2][0] = q0; b[nf2 * 2][1] = q1;
                b[nf2 * 2 + 1][0] = q2; b[nf2 * 2 + 1][1] = q3;
            }
#pragma unroll
            for (int nf = 0; nf < 8; nf++)
                mma_bf16(s[nf], aq[kf][0], aq[kf][1], aq[kf][2], aq[kf][3],
                         b[nf][0], b[nf][1]);
        }

        // ---- fixed-max softmax + group_prob/mask fold ----
#pragma unroll
        for (int rr = 0; rr < 2; rr++) {
            const __nv_bfloat16* grow = Gs + (rloc + rr * 8) * GPMPAD + tcol;
            float ls = 0.f;
#pragma unroll
            for (int nf = 0; nf < 8; nf++) {
                __nv_bfloat162 g2 = *(const __nv_bfloat162*)&grow[nf * 8];
                float gx = __bfloat162float(g2.x);
                float gy = __bfloat162float(g2.y);
                float e0 = exp2f(fmaf(s[nf][rr * 2], SC2, -M2));
                float e1 = exp2f(fmaf(s[nf][rr * 2 + 1], SC2, -M2));
                e0 = (gx >= 0.f) ? e0 : 0.f;
                e1 = (gy >= 0.f) ? e1 : 0.f;
                ls += e0 + e1;
                s[nf][rr * 2] = e0 * gx;
                s[nf][rr * 2 + 1] = e1 * gy;
            }
            l_run[rr] += ls;
        }

        // ---- O += P' V ----
#pragma unroll
        for (int kf = 0; kf < 4; kf++) {
            unsigned a0 = pack2(s[2 * kf][0], s[2 * kf][1]);
            unsigned a1 = pack2(s[2 * kf][2], s[2 * kf][3]);
            unsigned a2 = pack2(s[2 * kf + 1][0], s[2 * kf + 1][1]);
            unsigned a3 = pack2(s[2 * kf + 1][2], s[2 * kf + 1][3]);
#pragma unroll
            for (int df2 = 0; df2 < 8; df2++) {
                int row = kf * 16 + (lane & 7) + ((lane >> 3) & 1) * 8;
                int col = df2 * 16 + (lane >> 4) * 8;
                unsigned v0, v1, v2, v3;
                ldsm_x4_t(v0, v1, v2, v3, smem_u32(&Vs[row * APAD + col]));
                mma_bf16(o[2 * df2], a0, a1, a2, a3, v0, v1);
                mma_bf16(o[2 * df2 + 1], a0, a1, a2, a3, v2, v3);
            }
        }
        __syncthreads();
    }

    // final l reduction across the 4 lanes of each row
#pragma unroll
    for (int rr = 0; rr < 2; rr++) {
        l_run[rr] += __shfl_xor_sync(0xffffffffu, l_run[rr], 1);
        l_run[rr] += __shfl_xor_sync(0xffffffffu, l_run[rr], 2);
    }
    float inv0 = 1.f / l_run[0], inv1 = 1.f / l_run[1];
#pragma unroll
    for (int nf = 0; nf < 16; nf++) {
        int d = nf * 8 + tcol;
        __nv_bfloat162 p0, p1;
        p0.x = __float2bfloat16(o[nf][0] * inv0);
        p0.y = __float2bfloat16(o[nf][1] * inv0);
        p1.x = __float2bfloat16(o[nf][2] * inv1);
        p1.y = __float2bfloat16(o[nf][3] * inv1);
        *(__nv_bfloat162*)&g_zb[r0 * EMB + h * HD + d] = p0;
        *(__nv_bfloat162*)&g_zb[(r0 + 8) * EMB + h * HD + d] = p1;
    }
}

// ---------------------------------------------------------------------------
// LayerNorm over last dim (1024). One block per row.
// ---------------------------------------------------------------------------
__global__ __launch_bounds__(256) void ln_kernel(
    const float* __restrict__ gam, const float* __restrict__ bet,
    float* __restrict__ out)
{
    __shared__ float red[2][8];
    int s = blockIdx.x;
    int tid = threadIdx.x;
    const float* row = g_y + s * EMB;

    float4 x = *(const float4*)&row[tid * 4];
    float sum = x.x + x.y + x.z + x.w;
    float sq = x.x * x.x + x.y * x.y + x.z * x.z + x.w * x.w;
#pragma unroll
    for (int w = 16; w; w >>= 1) {
        sum += __shfl_xor_sync(0xffffffffu, sum, w);
        sq  += __shfl_xor_sync(0xffffffffu, sq, w);
    }
    if ((tid & 31) == 0) { red[0][tid >> 5] = sum; red[1][tid >> 5] = sq; }
    __syncthreads();
    if (tid < 32) {
        float s1 = (tid < 8) ? red[0][tid] : 0.f;
        float s2 = (tid < 8) ? red[1][tid] : 0.f;
#pragma unroll
        for (int w = 4; w; w >>= 1) {
            s1 += __shfl_xor_sync(0xffffffffu, s1, w);
            s2 += __shfl_xor_sync(0xffffffffu, s2, w);
        }
        if (tid == 0) { red[0][0] = s1; red[1][0] = s2; }
    }
    __syncthreads();
    float mu = red[0][0] * (1.f / EMB);
    float var = red[1][0] * (1.f / EMB) - mu * mu;
    float inv = rsqrtf(var + 1e-5f);

    float4 gg = *(const float4*)&gam[tid * 4];
    float4 bb = *(const float4*)&bet[tid * 4];
    float4 o;
    o.x = (x.x - mu) * inv * gg.x + bb.x;
    o.y = (x.y - mu) * inv * gg.y + bb.y;
    o.z = (x.z - mu) * inv * gg.z + bb.z;
    o.w = (x.w - mu) * inv * gg.w + bb.w;
    *(float4*)&out[s * EMB + tid * 4] = o;
}

// ---------------------------------------------------------------------------
extern "C" void kernel_launch(void* const* d_in, const int* in_sizes, int n_in,
                              void* d_out, int out_size)
{
    const float* q    = (const float*)d_in[0];
    const float* k    = (const float*)d_in[1];
    const float* v    = (const float*)d_in[2];
    const int*   mask = (const int*)  d_in[3];
    const float* gp   = (const float*)d_in[4];
    const float* Wq   = (const float*)d_in[5];
    const float* bq   = (const float*)d_in[6];
    const float* Wk   = (const float*)d_in[7];
    const float* bk   = (const float*)d_in[8];
    const float* Wv   = (const float*)d_in[9];
    const float* bv   = (const float*)d_in[10];
    const float* Wo   = (const float*)d_in[11];
    const float* bo   = (const float*)d_in[12];
    const float* lng  = (const float*)d_in[13];
    const float* lnb  = (const float*)d_in[14];
    float* out = (float*)d_out;

    cudaFuncSetAttribute(attn_bf16_kernel,
                         cudaFuncAttributeMaxDynamicSharedMemorySize,
                         ATTN_SMEM_BYTES);

    prep_gpm_kernel<<<SEQ * SEQ / (256 * 4), 256>>>(mask, gp);

    gemm_qkv_kernel<<<dim3(EMB / 128, SEQ / 128, 3), 256>>>(
        q, k, v, Wq, Wk, Wv, bq, bk, bv);

    attn_bf16_kernel<<<dim3(SEQ / 64, NH), 128, ATTN_SMEM_BYTES>>>();

    gemm_out_kernel<<<dim3(EMB / 128, SEQ / 128), 256>>>(Wo, bo, q);

    ln_kernel<<<SEQ, 256>>>(lng, lnb, out);
}

// round 5
// speedup vs baseline: 8.0776x; 1.0511x over previous
#include <cuda_runtime.h>
#include <cuda_bf16.h>
#include <math.h>

#define SEQ 4096
#define EMB 1024
#define NH 8
#define HD 128

// Scratch (no allocations allowed): __device__ globals.
__device__ __nv_bfloat16 g_qh[NH * SEQ * HD];
__device__ __nv_bfloat16 g_kh[NH * SEQ * HD];
__device__ __nv_bfloat16 g_vh[NH * SEQ * HD];
__device__ __nv_bfloat16 g_zb[SEQ * EMB];
__device__ __nv_bfloat16 g_gpm[SEQ * SEQ];       // mask? gp : -1  (bf16)
__device__ __nv_bfloat16 g_xb[3 * SEQ * EMB];    // q,k,v in bf16
__device__ __nv_bfloat16 g_wb[4 * EMB * EMB];    // Wq,Wk,Wv,Wo in bf16
__device__ float g_y[SEQ * EMB];

// ---------------------------------------------------------------------------
// helpers
// ---------------------------------------------------------------------------
__device__ __forceinline__ unsigned smem_u32(const void* p) {
    return (unsigned)__cvta_generic_to_shared(p);
}
__device__ __forceinline__ void cp16(void* dst, const void* src) {
    asm volatile("cp.async.cg.shared.global [%0],[%1],16;"
                 :: "r"(smem_u32(dst)), "l"(src));
}
__device__ __forceinline__ void cp_commit() {
    asm volatile("cp.async.commit_group;");
}
template <int N>
__device__ __forceinline__ void cp_wait() {
    asm volatile("cp.async.wait_group %0;" :: "n"(N));
}
__device__ __forceinline__ void ldsm_x4(unsigned& r0, unsigned& r1,
                                        unsigned& r2, unsigned& r3, unsigned addr) {
    asm volatile("ldmatrix.sync.aligned.m8n8.x4.shared.b16 {%0,%1,%2,%3},[%4];"
                 : "=r"(r0), "=r"(r1), "=r"(r2), "=r"(r3) : "r"(addr));
}
__device__ __forceinline__ void ldsm_x4_t(unsigned& r0, unsigned& r1,
                                          unsigned& r2, unsigned& r3, unsigned addr) {
    asm volatile("ldmatrix.sync.aligned.m8n8.x4.trans.shared.b16 {%0,%1,%2,%3},[%4];"
                 : "=r"(r0), "=r"(r1), "=r"(r2), "=r"(r3) : "r"(addr));
}
__device__ __forceinline__ void mma_bf16(float* c, unsigned a0, unsigned a1,
                                         unsigned a2, unsigned a3,
                                         unsigned b0, unsigned b1) {
    asm volatile(
        "mma.sync.aligned.m16n8k16.row.col.f32.bf16.bf16.f32 "
        "{%0,%1,%2,%3},{%4,%5,%6,%7},{%8,%9},{%0,%1,%2,%3};"
        : "+f"(c[0]), "+f"(c[1]), "+f"(c[2]), "+f"(c[3])
        : "r"(a0), "r"(a1), "r"(a2), "r"(a3), "r"(b0), "r"(b1));
}
__device__ __forceinline__ unsigned pack2(float lo, float hi) {
    __nv_bfloat162 h;
    h.x = __float2bfloat16(lo);
    h.y = __float2bfloat16(hi);
    return *(unsigned*)&h;
}

// ---------------------------------------------------------------------------
// prep kernels
// ---------------------------------------------------------------------------
__global__ __launch_bounds__(256) void prep_gpm_kernel(
    const int* __restrict__ mask, const float* __restrict__ gp)
{
    int idx = (blockIdx.x * 256 + threadIdx.x) * 4;
    int4 m = *(const int4*)&mask[idx];
    float4 g = *(const float4*)&gp[idx];
    __nv_bfloat16 o[4];
    o[0] = __float2bfloat16(m.x ? g.x : -1.f);
    o[1] = __float2bfloat16(m.y ? g.y : -1.f);
    o[2] = __float2bfloat16(m.z ? g.z : -1.f);
    o[3] = __float2bfloat16(m.w ? g.w : -1.f);
    *(uint2*)&g_gpm[idx] = *(uint2*)o;
}

__device__ __forceinline__ void conv8(const float* src, __nv_bfloat16* dst, int idx)
{
    float4 a = *(const float4*)&src[idx];
    float4 b = *(const float4*)&src[idx + 4];
    __nv_bfloat162 o[4];
    o[0].x = __float2bfloat16(a.x); o[0].y = __float2bfloat16(a.y);
    o[1].x = __float2bfloat16(a.z); o[1].y = __float2bfloat16(a.w);
    o[2].x = __float2bfloat16(b.x); o[2].y = __float2bfloat16(b.y);
    o[3].x = __float2bfloat16(b.z); o[3].y = __float2bfloat16(b.w);
    *(uint4*)&dst[idx] = *(uint4*)o;
}

__global__ __launch_bounds__(256) void conv_in_kernel(
    const float* __restrict__ q, const float* __restrict__ k,
    const float* __restrict__ v)
{
    int z = blockIdx.y;
    const float* src = (z == 0) ? q : (z == 1) ? k : v;
    conv8(src, g_xb + z * SEQ * EMB, (blockIdx.x * 256 + threadIdx.x) * 8);
}

__global__ __launch_bounds__(256) void conv_w_kernel(
    const float* __restrict__ Wq, const float* __restrict__ Wk,
    const float* __restrict__ Wv, const float* __restrict__ Wo)
{
    int z = blockIdx.y;
    const float* src = (z == 0) ? Wq : (z == 1) ? Wk : (z == 2) ? Wv : Wo;
    conv8(src, g_wb + z * EMB * EMB, (blockIdx.x * 256 + threadIdx.x) * 8);
}

// ---------------------------------------------------------------------------
// bf16 GEMM: C[m,n] = sum_k A[m,k]*W[n,k], A,W bf16, cp.async double buffered.
// BM=BN=128, BK=32, 256 threads = 8 warps (2m x 4n), warp tile 64x32.
// ---------------------------------------------------------------------------
#define GP 40   // bf16 row stride (32+8): 80B, conflict-free ldsm
#define GSTAGE (2 * 128 * GP)   // A+B per stage

__device__ __forceinline__ void gemm_stage_load(
    const __nv_bfloat16* A, const __nv_bfloat16* B,
    int m0, int n0, int k0, __nv_bfloat16* st)
{
    const int tid = threadIdx.x;
#pragma unroll
    for (int r = 0; r < 2; r++) {
        int idx = tid + 256 * r;
        int row = idx >> 2, ch = idx & 3;
        cp16(&st[row * GP + ch * 8], &A[(m0 + row) * EMB + k0 + ch * 8]);
        cp16(&st[128 * GP + row * GP + ch * 8], &B[(n0 + row) * EMB + k0 + ch * 8]);
    }
}

__device__ __forceinline__ void gemm_core(
    const __nv_bfloat16* A, const __nv_bfloat16* B,
    int m0, int n0, float c[4][4][4], __nv_bfloat16* gsm)
{
    const int tid = threadIdx.x, lane = tid & 31, w = tid >> 5;
    const int wm = (w >> 2) * 64, wn = (w & 3) * 32;

    gemm_stage_load(A, B, m0, n0, 0, gsm);
    cp_commit();

    for (int i = 0; i < EMB / 32; i++) {
        if (i + 1 < EMB / 32) {
            gemm_stage_load(A, B, m0, n0, (i + 1) * 32, gsm + ((i + 1) & 1) * GSTAGE);
            cp_commit();
            cp_wait<1>();
        } else {
            cp_wait<0>();
        }
        __syncthreads();

        __nv_bfloat16* Asm = gsm + (i & 1) * GSTAGE;
        __nv_bfloat16* Bsm = Asm + 128 * GP;
#pragma unroll
        for (int kk = 0; kk < 2; kk++) {
            unsigned a[4][4], b[4][2];
#pragma unroll
            for (int mf = 0; mf < 4; mf++) {
                int row = wm + mf * 16 + (lane & 15);
                int col = kk * 16 + (lane >> 4) * 8;
                ldsm_x4(a[mf][0], a[mf][1], a[mf][2], a[mf][3],
                        smem_u32(&Asm[row * GP + col]));
            }
#pragma unroll
            for (int nf2 = 0; nf2 < 2; nf2++) {
                int row = wn + nf2 * 16 + (lane & 7) + ((lane >> 4) << 3);
                int col = kk * 16 + ((lane >> 3) & 1) * 8;
                unsigned q0, q1, q2, q3;
                ldsm_x4(q0, q1, q2, q3, smem_u32(&Bsm[row * GP + col]));
                b[nf2 * 2][0] = q0; b[nf2 * 2][1] = q1;
                b[nf2 * 2 + 1][0] = q2; b[nf2 * 2 + 1][1] = q3;
            }
#pragma unroll
            for (int mf = 0; mf < 4; mf++)
#pragma unroll
                for (int nf = 0; nf < 4; nf++)
                    mma_bf16(c[mf][nf], a[mf][0], a[mf][1], a[mf][2], a[mf][3],
                             b[nf][0], b[nf][1]);
        }
        __syncthreads();
    }
}

__global__ __launch_bounds__(256) void gemm_qkv_kernel(
    const float* __restrict__ bq, const float* __restrict__ bk,
    const float* __restrict__ bv)
{
    __shared__ __nv_bfloat16 gsm[2 * GSTAGE];
    const int z = blockIdx.z;
    const __nv_bfloat16* A = g_xb + z * SEQ * EMB;
    const __nv_bfloat16* B = g_wb + z * EMB * EMB;
    const float* bias = (z == 0) ? bq : (z == 1) ? bk : bv;
    __nv_bfloat16* outp = (z == 0) ? g_qh : (z == 1) ? g_kh : g_vh;

    const int m0 = blockIdx.y * 128, n0 = blockIdx.x * 128;
    const int tid = threadIdx.x, lane = tid & 31, w = tid >> 5;
    const int wm = (w >> 2) * 64, wn = (w & 3) * 32;

    float c[4][4][4];
#pragma unroll
    for (int i = 0; i < 4; i++)
#pragma unroll
        for (int j = 0; j < 4; j++)
#pragma unroll
            for (int e = 0; e < 4; e++) c[i][j][e] = 0.f;

    gemm_core(A, B, m0, n0, c, gsm);

    const int rl = lane >> 2, cb = (lane & 3) * 2;
#pragma unroll
    for (int mf = 0; mf < 4; mf++) {
        int row0 = m0 + wm + mf * 16 + rl;
#pragma unroll
        for (int nf = 0; nf < 4; nf++) {
            int n = n0 + wn + nf * 8 + cb;
            float b0 = bias[n], b1 = bias[n + 1];
            int hh = n >> 7, d = n & 127;
            __nv_bfloat162 v0, v1;
            v0.x = __float2bfloat16(c[mf][nf][0] + b0);
            v0.y = __float2bfloat16(c[mf][nf][1] + b1);
            v1.x = __float2bfloat16(c[mf][nf][2] + b0);
            v1.y = __float2bfloat16(c[mf][nf][3] + b1);
            *(__nv_bfloat162*)&outp[(hh * SEQ + row0) * HD + d] = v0;
            *(__nv_bfloat162*)&outp[(hh * SEQ + row0 + 8) * HD + d] = v1;
        }
    }
}

__global__ __launch_bounds__(256) void gemm_out_kernel(
    const float* __restrict__ bo, const float* __restrict__ resid)
{
    __shared__ __nv_bfloat16 gsm[2 * GSTAGE];
    const int m0 = blockIdx.y * 128, n0 = blockIdx.x * 128;
    const int tid = threadIdx.x, lane = tid & 31, w = tid >> 5;
    const int wm = (w >> 2) * 64, wn = (w & 3) * 32;

    float c[4][4][4];
#pragma unroll
    for (int i = 0; i < 4; i++)
#pragma unroll
        for (int j = 0; j < 4; j++)
#pragma unroll
            for (int e = 0; e < 4; e++) c[i][j][e] = 0.f;

    gemm_core(g_zb, g_wb + 3 * EMB * EMB, m0, n0, c, gsm);

    const int rl = lane >> 2, cb = (lane & 3) * 2;
#pragma unroll
    for (int mf = 0; mf < 4; mf++) {
        int row0 = m0 + wm + mf * 16 + rl;
#pragma unroll
        for (int nf = 0; nf < 4; nf++) {
            int n = n0 + wn + nf * 8 + cb;
            float b0 = bo[n], b1 = bo[n + 1];
            float2 r0v = *(const float2*)&resid[row0 * EMB + n];
            float2 r1v = *(const float2*)&resid[(row0 + 8) * EMB + n];
            float2 y0 = {c[mf][nf][0] + b0 + r0v.x, c[mf][nf][1] + b1 + r0v.y};
            float2 y1 = {c[mf][nf][2] + b0 + r1v.x, c[mf][nf][3] + b1 + r1v.y};
            *(float2*)&g_y[row0 * EMB + n] = y0;
            *(float2*)&g_y[(row0 + 8) * EMB + n] = y1;
        }
    }
}

// ---------------------------------------------------------------------------
// Flash attention, bf16 MMA, fixed-max softmax.
// Q fragments loaded directly from global (no Q smem); K,gpm double buffered
// via cp.async; V single buffered (load overlaps S-MMA + softmax).
// smem ~69KB -> 3 CTAs/SM.
// ---------------------------------------------------------------------------
#define APAD 136
#define GPMPAD 72
#define KV_ELEMS (64 * APAD)
#define G_ELEMS (64 * GPMPAD)
// layout: K0 | K1 | V | G0 | G1
#define OFF_K(st) ((st) * KV_ELEMS)
#define OFF_V     (2 * KV_ELEMS)
#define OFF_G(st) (3 * KV_ELEMS + (st) * G_ELEMS)
#define ATTN_SMEM_BYTES ((3 * KV_ELEMS + 2 * G_ELEMS) * 2)

__global__ __launch_bounds__(128, 3) void attn_bf16_kernel()
{
    extern __shared__ __nv_bfloat16 sm_[];
    const int h = blockIdx.y, s0 = blockIdx.x * 64;
    const int tid = threadIdx.x, lane = tid & 31, w = tid >> 5;
    const float SC2 = 0.12751744f;   // log2(e)/sqrt(128)
    const float M2 = 11.541560f;     // 8*log2(e)

    const __nv_bfloat16* Qg = g_qh + h * SEQ * HD;
    const __nv_bfloat16* Kg = g_kh + h * SEQ * HD;
    const __nv_bfloat16* Vg = g_vh + h * SEQ * HD;

    // ---- prefetch tile 0 of K/gpm ----
#pragma unroll
    for (int r = 0; r < 8; r++) {
        int idx = tid + 128 * r;
        int row = idx >> 4, ch = idx & 15;
        cp16(&sm_[OFF_K(0) + row * APAD + ch * 8], &Kg[row * HD + ch * 8]);
    }
#pragma unroll
    for (int r = 0; r < 4; r++) {
        int idx = tid + 128 * r;
        int row = idx >> 3, ch = idx & 7;
        cp16(&sm_[OFF_G(0) + row * GPMPAD + ch * 8],
             &g_gpm[(s0 + row) * SEQ + ch * 8]);
    }
    cp_commit();

    // ---- load Q fragments directly from global ----
    unsigned aq[8][4];
    {
        int row = s0 + w * 16 + (lane >> 2);
        int col = (lane & 3) * 2;
#pragma unroll
        for (int kf = 0; kf < 8; kf++) {
            aq[kf][0] = *(const unsigned*)&Qg[row * HD + kf * 16 + col];
            aq[kf][1] = *(const unsigned*)&Qg[(row + 8) * HD + kf * 16 + col];
            aq[kf][2] = *(const unsigned*)&Qg[row * HD + kf * 16 + col + 8];
            aq[kf][3] = *(const unsigned*)&Qg[(row + 8) * HD + kf * 16 + col + 8];
        }
    }

    float o[16][4];
    float l_run[2] = {0.f, 0.f};
#pragma unroll
    for (int nf = 0; nf < 16; nf++)
#pragma unroll
        for (int e = 0; e < 4; e++) o[nf][e] = 0.f;

    const int rloc = w * 16 + (lane >> 2);
    const int r0 = s0 + rloc;
    const int tcol = (lane & 3) * 2;

    for (int i = 0; i < SEQ / 64; i++) {
        cp_wait<0>();       // K_i, G_i ready
        __syncthreads();    // + V buffer free

        const int st = i & 1;
        const __nv_bfloat16* Ks = sm_ + OFF_K(st);
        const __nv_bfloat16* Vs = sm_ + OFF_V;
        const __nv_bfloat16* Gs = sm_ + OFF_G(st);

        // issue V_i
#pragma unroll
        for (int r = 0; r < 8; r++) {
            int idx = tid + 128 * r;
            int row = idx >> 4, ch = idx & 15;
            cp16(&sm_[OFF_V + row * APAD + ch * 8],
                 &Vg[(i * 64 + row) * HD + ch * 8]);
        }
        cp_commit();

        // issue K_{i+1}, G_{i+1}
        if (i + 1 < SEQ / 64) {
            const int t1 = (i + 1) * 64;
#pragma unroll
            for (int r = 0; r < 8; r++) {
                int idx = tid + 128 * r;
                int row = idx >> 4, ch = idx & 15;
                cp16(&sm_[OFF_K(st ^ 1) + row * APAD + ch * 8],
                     &Kg[(t1 + row) * HD + ch * 8]);
            }
#pragma unroll
            for (int r = 0; r < 4; r++) {
                int idx = tid + 128 * r;
                int row = idx >> 3, ch = idx & 7;
                cp16(&sm_[OFF_G(st ^ 1) + row * GPMPAD + ch * 8],
                     &g_gpm[(s0 + row) * SEQ + t1 + ch * 8]);
            }
            cp_commit();
        }

        // ---- S = Q K^T ----
        float s[8][4];
#pragma unroll
        for (int nf = 0; nf < 8; nf++)
#pragma unroll
            for (int e = 0; e < 4; e++) s[nf][e] = 0.f;

#pragma unroll
        for (int kf = 0; kf < 8; kf++) {
            unsigned b[8][2];
#pragma unroll
            for (int nf2 = 0; nf2 < 4; nf2++) {
                int row = nf2 * 16 + (lane & 7) + ((lane >> 4) << 3);
                int col = kf * 16 + ((lane >> 3) & 1) * 8;
                unsigned q0, q1, q2, q3;
                ldsm_x4(q0, q1, q2, q3, smem_u32(&Ks[row * APAD + col]));
                b[nf2 * 2][0] = q0; b[nf2 * 2][1] = q1;
                b[nf2 * 2 + 1][0] = q2; b[nf2 * 2 + 1][1] = q3;
            }
#pragma unroll
            for (int nf = 0; nf < 8; nf++)
                mma_bf16(s[nf], aq[kf][0], aq[kf][1], aq[kf][2], aq[kf][3],
                         b[nf][0], b[nf][1]);
        }

        // ---- fixed-max softmax + group_prob/mask fold ----
#pragma unroll
        for (int rr = 0; rr < 2; rr++) {
            const __nv_bfloat16* grow = Gs + (rloc + rr * 8) * GPMPAD + tcol;
            float ls = 0.f;
#pragma unroll
            for (int nf = 0; nf < 8; nf++) {
                __nv_bfloat162 g2 = *(const __nv_bfloat162*)&grow[nf * 8];
                float gx = __bfloat162float(g2.x);
                float gy = __bfloat162float(g2.y);
                float e0 = exp2f(fmaf(s[nf][rr * 2], SC2, -M2));
                float e1 = exp2f(fmaf(s[nf][rr * 2 + 1], SC2, -M2));
                e0 = (gx >= 0.f) ? e0 : 0.f;
                e1 = (gy >= 0.f) ? e1 : 0.f;
                ls += e0 + e1;
                s[nf][rr * 2] = e0 * gx;
                s[nf][rr * 2 + 1] = e1 * gy;
            }
            l_run[rr] += ls;
        }

        // ---- wait V, then O += P' V ----
        if (i + 1 < SEQ / 64) cp_wait<1>(); else cp_wait<0>();
        __syncthreads();

#pragma unroll
        for (int kf = 0; kf < 4; kf++) {
            unsigned a0 = pack2(s[2 * kf][0], s[2 * kf][1]);
            unsigned a1 = pack2(s[2 * kf][2], s[2 * kf][3]);
            unsigned a2 = pack2(s[2 * kf + 1][0], s[2 * kf + 1][1]);
            unsigned a3 = pack2(s[2 * kf + 1][2], s[2 * kf + 1][3]);
#pragma unroll
            for (int df2 = 0; df2 < 8; df2++) {
                int row = kf * 16 + (lane & 7) + ((lane >> 3) & 1) * 8;
                int col = df2 * 16 + (lane >> 4) * 8;
                unsigned v0, v1, v2, v3;
                ldsm_x4_t(v0, v1, v2, v3, smem_u32(&Vs[row * APAD + col]));
                mma_bf16(o[2 * df2], a0, a1, a2, a3, v0, v1);
                mma_bf16(o[2 * df2 + 1], a0, a1, a2, a3, v2, v3);
            }
        }
    }

    // final l reduction across the 4 lanes of each row
#pragma unroll
    for (int rr = 0; rr < 2; rr++) {
        l_run[rr] += __shfl_xor_sync(0xffffffffu, l_run[rr], 1);
        l_run[rr] += __shfl_xor_sync(0xffffffffu, l_run[rr], 2);
    }
    float inv0 = 1.f / l_run[0], inv1 = 1.f / l_run[1];
#pragma unroll
    for (int nf = 0; nf < 16; nf++) {
        int d = nf * 8 + tcol;
        __nv_bfloat162 p0, p1;
        p0.x = __float2bfloat16(o[nf][0] * inv0);
        p0.y = __float2bfloat16(o[nf][1] * inv0);
        p1.x = __float2bfloat16(o[nf][2] * inv1);
        p1.y = __float2bfloat16(o[nf][3] * inv1);
        *(__nv_bfloat162*)&g_zb[r0 * EMB + h * HD + d] = p0;
        *(__nv_bfloat162*)&g_zb[(r0 + 8) * EMB + h * HD + d] = p1;
    }
}

// ---------------------------------------------------------------------------
// LayerNorm over last dim (1024). One block per row.
// ---------------------------------------------------------------------------
__global__ __launch_bounds__(256) void ln_kernel(
    const float* __restrict__ gam, const float* __restrict__ bet,
    float* __restrict__ out)
{
    __shared__ float red[2][8];
    int s = blockIdx.x;
    int tid = threadIdx.x;
    const float* row = g_y + s * EMB;

    float4 x = *(const float4*)&row[tid * 4];
    float sum = x.x + x.y + x.z + x.w;
    float sq = x.x * x.x + x.y * x.y + x.z * x.z + x.w * x.w;
#pragma unroll
    for (int w = 16; w; w >>= 1) {
        sum += __shfl_xor_sync(0xffffffffu, sum, w);
        sq  += __shfl_xor_sync(0xffffffffu, sq, w);
    }
    if ((tid & 31) == 0) { red[0][tid >> 5] = sum; red[1][tid >> 5] = sq; }
    __syncthreads();
    if (tid < 32) {
        float s1 = (tid < 8) ? red[0][tid] : 0.f;
        float s2 = (tid < 8) ? red[1][tid] : 0.f;
#pragma unroll
        for (int w = 4; w; w >>= 1) {
            s1 += __shfl_xor_sync(0xffffffffu, s1, w);
            s2 += __shfl_xor_sync(0xffffffffu, s2, w);
        }
        if (tid == 0) { red[0][0] = s1; red[1][0] = s2; }
    }
    __syncthreads();
    float mu = red[0][0] * (1.f / EMB);
    float var = red[1][0] * (1.f / EMB) - mu * mu;
    float inv = rsqrtf(var + 1e-5f);

    float4 gg = *(const float4*)&gam[tid * 4];
    float4 bb = *(const float4*)&bet[tid * 4];
    float4 o;
    o.x = (x.x - mu) * inv * gg.x + bb.x;
    o.y = (x.y - mu) * inv * gg.y + bb.y;
    o.z = (x.z - mu) * inv * gg.z + bb.z;
    o.w = (x.w - mu) * inv * gg.w + bb.w;
    *(float4*)&out[s * EMB + tid * 4] = o;
}

// ---------------------------------------------------------------------------
extern "C" void kernel_launch(void* const* d_in, const int* in_sizes, int n_in,
                              void* d_out, int out_size)
{
    const float* q    = (const float*)d_in[0];
    const float* k    = (const float*)d_in[1];
    const float* v    = (const float*)d_in[2];
    const int*   mask = (const int*)  d_in[3];
    const float* gp   = (const float*)d_in[4];
    const float* Wq   = (const float*)d_in[5];
    const float* bq   = (const float*)d_in[6];
    const float* Wk   = (const float*)d_in[7];
    const float* bk   = (const float*)d_in[8];
    const float* Wv   = (const float*)d_in[9];
    const float* bv   = (const float*)d_in[10];
    const float* Wo   = (const float*)d_in[11];
    const float* bo   = (const float*)d_in[12];
    const float* lng  = (const float*)d_in[13];
    const float* lnb  = (const float*)d_in[14];
    float* out = (float*)d_out;

    cudaFuncSetAttribute(attn_bf16_kernel,
                         cudaFuncAttributeMaxDynamicSharedMemorySize,
                         ATTN_SMEM_BYTES);

    conv_in_kernel<<<dim3(SEQ * EMB / (256 * 8), 3), 256>>>(q, k, v);
    conv_w_kernel<<<dim3(EMB * EMB / (256 * 8), 4), 256>>>(Wq, Wk, Wv, Wo);
    prep_gpm_kernel<<<SEQ * SEQ / (256 * 4), 256>>>(mask, gp);

    gemm_qkv_kernel<<<dim3(EMB / 128, SEQ / 128, 3), 256>>>(bq, bk, bv);

    attn_bf16_kernel<<<dim3(SEQ / 64, NH), 128, ATTN_SMEM_BYTES>>>();

    gemm_out_kernel<<<dim3(EMB / 128, SEQ / 128), 256>>>(bo, q);

    ln_kernel<<<SEQ, 256>>>(lng, lnb, out);
}

// round 9
// speedup vs baseline: 8.7669x; 1.0853x over previous
#include <cuda_runtime.h>
#include <cuda_bf16.h>
#include <math.h>

#define SEQ 4096
#define EMB 1024
#define NH 8
#define HD 128

// Scratch (no allocations allowed): __device__ globals.
__device__ __nv_bfloat16 g_qh[NH * SEQ * HD];
__device__ __nv_bfloat16 g_kh[NH * SEQ * HD];
__device__ __nv_bfloat16 g_vh[NH * SEQ * HD];
__device__ __nv_bfloat16 g_zb[SEQ * EMB];
__device__ __nv_bfloat16 g_gpm[SEQ * SEQ];       // mask? gp : -1  (bf16)
__device__ __nv_bfloat16 g_xb[3 * SEQ * EMB];    // q,k,v in bf16
__device__ __nv_bfloat16 g_wb[4 * EMB * EMB];    // Wq,Wk,Wv,Wo in bf16
__device__ float g_y[SEQ * EMB];

// ---------------------------------------------------------------------------
// helpers
// ---------------------------------------------------------------------------
__device__ __forceinline__ unsigned smem_u32(const void* p) {
    return (unsigned)__cvta_generic_to_shared(p);
}
__device__ __forceinline__ void cp16(void* dst, const void* src) {
    asm volatile("cp.async.cg.shared.global [%0],[%1],16;"
                 :: "r"(smem_u32(dst)), "l"(src));
}
__device__ __forceinline__ void cp_commit() {
    asm volatile("cp.async.commit_group;");
}
template <int N>
__device__ __forceinline__ void cp_wait() {
    asm volatile("cp.async.wait_group %0;" :: "n"(N));
}
__device__ __forceinline__ void ldsm_x4(unsigned& r0, unsigned& r1,
                                        unsigned& r2, unsigned& r3, unsigned addr) {
    asm volatile("ldmatrix.sync.aligned.m8n8.x4.shared.b16 {%0,%1,%2,%3},[%4];"
                 : "=r"(r0), "=r"(r1), "=r"(r2), "=r"(r3) : "r"(addr));
}
__device__ __forceinline__ void ldsm_x4_t(unsigned& r0, unsigned& r1,
                                          unsigned& r2, unsigned& r3, unsigned addr) {
    asm volatile("ldmatrix.sync.aligned.m8n8.x4.trans.shared.b16 {%0,%1,%2,%3},[%4];"
                 : "=r"(r0), "=r"(r1), "=r"(r2), "=r"(r3) : "r"(addr));
}
__device__ __forceinline__ void mma_bf16(float* c, unsigned a0, unsigned a1,
                                         unsigned a2, unsigned a3,
                                         unsigned b0, unsigned b1) {
    asm volatile(
        "mma.sync.aligned.m16n8k16.row.col.f32.bf16.bf16.f32 "
        "{%0,%1,%2,%3},{%4,%5,%6,%7},{%8,%9},{%0,%1,%2,%3};"
        : "+f"(c[0]), "+f"(c[1]), "+f"(c[2]), "+f"(c[3])
        : "r"(a0), "r"(a1), "r"(a2), "r"(a3), "r"(b0), "r"(b1));
}
__device__ __forceinline__ unsigned pack2(float lo, float hi) {
    __nv_bfloat162 h;
    h.x = __float2bfloat16(lo);
    h.y = __float2bfloat16(hi);
    return *(unsigned*)&h;
}

// ---------------------------------------------------------------------------
// prep kernels
// ---------------------------------------------------------------------------
__global__ __launch_bounds__(256) void prep_gpm_kernel(
    const int* __restrict__ mask, const float* __restrict__ gp)
{
    int idx = (blockIdx.x * 256 + threadIdx.x) * 4;
    int4 m = *(const int4*)&mask[idx];
    float4 g = *(const float4*)&gp[idx];
    __nv_bfloat16 o[4];
    o[0] = __float2bfloat16(m.x ? g.x : -1.f);
    o[1] = __float2bfloat16(m.y ? g.y : -1.f);
    o[2] = __float2bfloat16(m.z ? g.z : -1.f);
    o[3] = __float2bfloat16(m.w ? g.w : -1.f);
    *(uint2*)&g_gpm[idx] = *(uint2*)o;
}

__device__ __forceinline__ void conv8(const float* src, __nv_bfloat16* dst, int idx)
{
    float4 a = *(const float4*)&src[idx];
    float4 b = *(const float4*)&src[idx + 4];
    __nv_bfloat162 o[4];
    o[0].x = __float2bfloat16(a.x); o[0].y = __float2bfloat16(a.y);
    o[1].x = __float2bfloat16(a.z); o[1].y = __float2bfloat16(a.w);
    o[2].x = __float2bfloat16(b.x); o[2].y = __float2bfloat16(b.y);
    o[3].x = __float2bfloat16(b.z); o[3].y = __float2bfloat16(b.w);
    *(uint4*)&dst[idx] = *(uint4*)o;
}

__global__ __launch_bounds__(256) void conv_in_kernel(
    const float* __restrict__ q, const float* __restrict__ k,
    const float* __restrict__ v)
{
    int z = blockIdx.y;
    const float* src = (z == 0) ? q : (z == 1) ? k : v;
    conv8(src, g_xb + z * SEQ * EMB, (blockIdx.x * 256 + threadIdx.x) * 8);
}

__global__ __launch_bounds__(256) void conv_w_kernel(
    const float* __restrict__ Wq, const float* __restrict__ Wk,
    const float* __restrict__ Wv, const float* __restrict__ Wo)
{
    int z = blockIdx.y;
    const float* src = (z == 0) ? Wq : (z == 1) ? Wk : (z == 2) ? Wv : Wo;
    conv8(src, g_wb + z * EMB * EMB, (blockIdx.x * 256 + threadIdx.x) * 8);
}

// ---------------------------------------------------------------------------
// bf16 GEMM: C[m,n] = sum_k A[m,k]*W[n,k], A,W bf16, cp.async 3-stage pipeline.
// BM=BN=128, BK=32, 256 threads = 8 warps (2m x 4n), warp tile 64x32.
// ---------------------------------------------------------------------------
#define GP 40                   // bf16 row stride (32+8): 80B, conflict-free ldsm
#define GSTAGE (2 * 128 * GP)   // A+B per stage (elements)
#define GEMM_SMEM_BYTES (3 * GSTAGE * 2)
#define NKSLAB (EMB / 32)       // 32

__device__ __forceinline__ void gemm_stage_load(
    const __nv_bfloat16* A, const __nv_bfloat16* B,
    int m0, int n0, int k0, __nv_bfloat16* st)
{
    const int tid = threadIdx.x;
#pragma unroll
    for (int r = 0; r < 2; r++) {
        int idx = tid + 256 * r;
        int row = idx >> 2, ch = idx & 3;
        cp16(&st[row * GP + ch * 8], &A[(m0 + row) * EMB + k0 + ch * 8]);
        cp16(&st[128 * GP + row * GP + ch * 8], &B[(n0 + row) * EMB + k0 + ch * 8]);
    }
}

__device__ __forceinline__ void gemm_core(
    const __nv_bfloat16* A, const __nv_bfloat16* B,
    int m0, int n0, float c[4][4][4], __nv_bfloat16* gsm)
{
    const int tid = threadIdx.x, lane = tid & 31, w = tid >> 5;
    const int wm = (w >> 2) * 64, wn = (w & 3) * 32;

    gemm_stage_load(A, B, m0, n0, 0, gsm);
    cp_commit();
    gemm_stage_load(A, B, m0, n0, 32, gsm + GSTAGE);
    cp_commit();

    for (int i = 0; i < NKSLAB; i++) {
        if (i + 2 < NKSLAB) {
            gemm_stage_load(A, B, m0, n0, (i + 2) * 32,
                            gsm + ((i + 2) % 3) * GSTAGE);
            cp_commit();
            cp_wait<2>();
        } else if (i + 1 < NKSLAB) {
            cp_wait<1>();
        } else {
            cp_wait<0>();
        }
        __syncthreads();

        __nv_bfloat16* Asm = gsm + (i % 3) * GSTAGE;
        __nv_bfloat16* Bsm = Asm + 128 * GP;
#pragma unroll
        for (int kk = 0; kk < 2; kk++) {
            unsigned a[4][4], b[4][2];
#pragma unroll
            for (int mf = 0; mf < 4; mf++) {
                int row = wm + mf * 16 + (lane & 15);
                int col = kk * 16 + (lane >> 4) * 8;
                ldsm_x4(a[mf][0], a[mf][1], a[mf][2], a[mf][3],
                        smem_u32(&Asm[row * GP + col]));
            }
#pragma unroll
            for (int nf2 = 0; nf2 < 2; nf2++) {
                int row = wn + nf2 * 16 + (lane & 7) + ((lane >> 4) << 3);
                int col = kk * 16 + ((lane >> 3) & 1) * 8;
                unsigned q0, q1, q2, q3;
                ldsm_x4(q0, q1, q2, q3, smem_u32(&Bsm[row * GP + col]));
                b[nf2 * 2][0] = q0; b[nf2 * 2][1] = q1;
                b[nf2 * 2 + 1][0] = q2; b[nf2 * 2 + 1][1] = q3;
            }
#pragma unroll
            for (int mf = 0; mf < 4; mf++)
#pragma unroll
                for (int nf = 0; nf < 4; nf++)
                    mma_bf16(c[mf][nf], a[mf][0], a[mf][1], a[mf][2], a[mf][3],
                             b[nf][0], b[nf][1]);
        }
        __syncthreads();
    }
}

__global__ __launch_bounds__(256) void gemm_qkv_kernel(
    const float* __restrict__ bq, const float* __restrict__ bk,
    const float* __restrict__ bv)
{
    extern __shared__ __nv_bfloat16 gsm[];
    const int z = blockIdx.z;
    const __nv_bfloat16* A = g_xb + z * SEQ * EMB;
    const __nv_bfloat16* B = g_wb + z * EMB * EMB;
    const float* bias = (z == 0) ? bq : (z == 1) ? bk : bv;
    __nv_bfloat16* outp = (z == 0) ? g_qh : (z == 1) ? g_kh : g_vh;

    const int m0 = blockIdx.y * 128, n0 = blockIdx.x * 128;
    const int tid = threadIdx.x, lane = tid & 31, w = tid >> 5;
    const int wm = (w >> 2) * 64, wn = (w & 3) * 32;

    float c[4][4][4];
#pragma unroll
    for (int i = 0; i < 4; i++)
#pragma unroll
        for (int j = 0; j < 4; j++)
#pragma unroll
            for (int e = 0; e < 4; e++) c[i][j][e] = 0.f;

    gemm_core(A, B, m0, n0, c, gsm);

    const int rl = lane >> 2, cb = (lane & 3) * 2;
#pragma unroll
    for (int mf = 0; mf < 4; mf++) {
        int row0 = m0 + wm + mf * 16 + rl;
#pragma unroll
        for (int nf = 0; nf < 4; nf++) {
            int n = n0 + wn + nf * 8 + cb;
            float b0 = bias[n], b1 = bias[n + 1];
            int hh = n >> 7, d = n & 127;
            __nv_bfloat162 v0, v1;
            v0.x = __float2bfloat16(c[mf][nf][0] + b0);
            v0.y = __float2bfloat16(c[mf][nf][1] + b1);
            v1.x = __float2bfloat16(c[mf][nf][2] + b0);
            v1.y = __float2bfloat16(c[mf][nf][3] + b1);
            *(__nv_bfloat162*)&outp[(hh * SEQ + row0) * HD + d] = v0;
            *(__nv_bfloat162*)&outp[(hh * SEQ + row0 + 8) * HD + d] = v1;
        }
    }
}

__global__ __launch_bounds__(256) void gemm_out_kernel(
    const float* __restrict__ bo, const float* __restrict__ resid)
{
    extern __shared__ __nv_bfloat16 gsm[];
    const int m0 = blockIdx.y * 128, n0 = blockIdx.x * 128;
    const int tid = threadIdx.x, lane = tid & 31, w = tid >> 5;
    const int wm = (w >> 2) * 64, wn = (w & 3) * 32;

    float c[4][4][4];
#pragma unroll
    for (int i = 0; i < 4; i++)
#pragma unroll
        for (int j = 0; j < 4; j++)
#pragma unroll
            for (int e = 0; e < 4; e++) c[i][j][e] = 0.f;

    gemm_core(g_zb, g_wb + 3 * EMB * EMB, m0, n0, c, gsm);

    const int rl = lane >> 2, cb = (lane & 3) * 2;
#pragma unroll
    for (int mf = 0; mf < 4; mf++) {
        int row0 = m0 + wm + mf * 16 + rl;
#pragma unroll
        for (int nf = 0; nf < 4; nf++) {
            int n = n0 + wn + nf * 8 + cb;
            float b0 = bo[n], b1 = bo[n + 1];
            float2 r0v = *(const float2*)&resid[row0 * EMB + n];
            float2 r1v = *(const float2*)&resid[(row0 + 8) * EMB + n];
            float2 y0 = {c[mf][nf][0] + b0 + r0v.x, c[mf][nf][1] + b1 + r0v.y};
            float2 y1 = {c[mf][nf][2] + b0 + r1v.x, c[mf][nf][3] + b1 + r1v.y};
            *(float2*)&g_y[row0 * EMB + n] = y0;
            *(float2*)&g_y[(row0 + 8) * EMB + n] = y1;
        }
    }
}

// ---------------------------------------------------------------------------
// Flash attention, bf16 MMA, fixed-max softmax.
// 256 threads (8 warps), q-tile 128 rows (16 per warp), kv tile 64.
// Q fragments from global; K,gpm double buffered; V single buffered.
// smem ~87KB -> 2 CTAs/SM (16 warps/SM).
// ---------------------------------------------------------------------------
#define APAD 136
#define GPMPAD 72
#define KV_ELEMS (64 * APAD)
#define G_ELEMS (128 * GPMPAD)
// layout: K0 | K1 | V | G0 | G1
#define OFF_K(st) ((st) * KV_ELEMS)
#define OFF_V     (2 * KV_ELEMS)
#define OFF_G(st) (3 * KV_ELEMS + (st) * G_ELEMS)
#define ATTN_SMEM_BYTES ((3 * KV_ELEMS + 2 * G_ELEMS) * 2)

__global__ __launch_bounds__(256, 2) void attn_bf16_kernel()
{
    extern __shared__ __nv_bfloat16 sm_[];
    const int h = blockIdx.y, s0 = blockIdx.x * 128;
    const int tid = threadIdx.x, lane = tid & 31, w = tid >> 5;
    const float SC2 = 0.12751744f;   // log2(e)/sqrt(128)
    const float M2 = 11.541560f;     // 8*log2(e)

    const __nv_bfloat16* Qg = g_qh + h * SEQ * HD;
    const __nv_bfloat16* Kg = g_kh + h * SEQ * HD;
    const __nv_bfloat16* Vg = g_vh + h * SEQ * HD;

    // ---- prefetch tile 0 of K (64x128) and gpm (128x64) ----
#pragma unroll
    for (int r = 0; r < 4; r++) {
        int idx = tid + 256 * r;
        int row = idx >> 4, ch = idx & 15;
        cp16(&sm_[OFF_K(0) + row * APAD + ch * 8], &Kg[row * HD + ch * 8]);
    }
#pragma unroll
    for (int r = 0; r < 4; r++) {
        int idx = tid + 256 * r;
        int row = idx >> 3, ch = idx & 7;
        cp16(&sm_[OFF_G(0) + row * GPMPAD + ch * 8],
             &g_gpm[(s0 + row) * SEQ + ch * 8]);
    }
    cp_commit();

    // ---- load Q fragments directly from global ----
    unsigned aq[8][4];
    {
        int row = s0 + w * 16 + (lane >> 2);
        int col = (lane & 3) * 2;
#pragma unroll
        for (int kf = 0; kf < 8; kf++) {
            aq[kf][0] = *(const unsigned*)&Qg[row * HD + kf * 16 + col];
            aq[kf][1] = *(const unsigned*)&Qg[(row + 8) * HD + kf * 16 + col];
            aq[kf][2] = *(const unsigned*)&Qg[row * HD + kf * 16 + col + 8];
            aq[kf][3] = *(const unsigned*)&Qg[(row + 8) * HD + kf * 16 + col + 8];
        }
    }

    float o[16][4];
    float l_run[2] = {0.f, 0.f};
#pragma unroll
    for (int nf = 0; nf < 16; nf++)
#pragma unroll
        for (int e = 0; e < 4; e++) o[nf][e] = 0.f;

    const int rloc = w * 16 + (lane >> 2);   // local q row 0..127
    const int r0 = s0 + rloc;
    const int tcol = (lane & 3) * 2;

    for (int i = 0; i < SEQ / 64; i++) {
        cp_wait<0>();       // K_i, G_i ready (and prior V consumed-by-wait)
        __syncthreads();    // + V buffer free across warps

        const int st = i & 1;
        const __nv_bfloat16* Ks = sm_ + OFF_K(st);
        const __nv_bfloat16* Vs = sm_ + OFF_V;
        const __nv_bfloat16* Gs = sm_ + OFF_G(st);

        // issue V_i
#pragma unroll
        for (int r = 0; r < 4; r++) {
            int idx = tid + 256 * r;
            int row = idx >> 4, ch = idx & 15;
            cp16(&sm_[OFF_V + row * APAD + ch * 8],
                 &Vg[(i * 64 + row) * HD + ch * 8]);
        }
        cp_commit();

        // issue K_{i+1}, G_{i+1}
        if (i + 1 < SEQ / 64) {
            const int t1 = (i + 1) * 64;
#pragma unroll
            for (int r = 0; r < 4; r++) {
                int idx = tid + 256 * r;
                int row = idx >> 4, ch = idx & 15;
                cp16(&sm_[OFF_K(st ^ 1) + row * APAD + ch * 8],
                     &Kg[(t1 + row) * HD + ch * 8]);
            }
#pragma unroll
            for (int r = 0; r < 4; r++) {
                int idx = tid + 256 * r;
                int row = idx >> 3, ch = idx & 7;
                cp16(&sm_[OFF_G(st ^ 1) + row * GPMPAD + ch * 8],
                     &g_gpm[(s0 + row) * SEQ + t1 + ch * 8]);
            }
            cp_commit();
        }

        // ---- S = Q K^T ----
        float s[8][4];
#pragma unroll
        for (int nf = 0; nf < 8; nf++)
#pragma unroll
            for (int e = 0; e < 4; e++) s[nf][e] = 0.f;

#pragma unroll
        for (int kf = 0; kf < 8; kf++) {
            unsigned b[8][2];
#pragma unroll
            for (int nf2 = 0; nf2 < 4; nf2++) {
                int row = nf2 * 16 + (lane & 7) + ((lane >> 4) << 3);
                int col = kf * 16 + ((lane >> 3) & 1) * 8;
                unsigned q0, q1, q2, q3;
                ldsm_x4(q0, q1, q2, q3, smem_u32(&Ks[row * APAD + col]));
                b[nf2 * 2][0] = q0; b[nf2 * 2][1] = q1;
                b[nf2 * 2 + 1][0] = q2; b[nf2 * 2 + 1][1] = q3;
            }
#pragma unroll
            for (int nf = 0; nf < 8; nf++)
                mma_bf16(s[nf], aq[kf][0], aq[kf][1], aq[kf][2], aq[kf][3],
                         b[nf][0], b[nf][1]);
        }

        // ---- fixed-max softmax + group_prob/mask fold ----
#pragma unroll
        for (int rr = 0; rr < 2; rr++) {
            const __nv_bfloat16* grow = Gs + (rloc + rr * 8) * GPMPAD + tcol;
            float ls = 0.f;
#pragma unroll
            for (int nf = 0; nf < 8; nf++) {
                __nv_bfloat162 g2 = *(const __nv_bfloat162*)&grow[nf * 8];
                float gx = __bfloat162float(g2.x);
                float gy = __bfloat162float(g2.y);
                float e0 = exp2f(fmaf(s[nf][rr * 2], SC2, -M2));
                float e1 = exp2f(fmaf(s[nf][rr * 2 + 1], SC2, -M2));
                e0 = (gx >= 0.f) ? e0 : 0.f;
                e1 = (gy >= 0.f) ? e1 : 0.f;
                ls += e0 + e1;
                s[nf][rr * 2] = e0 * gx;
                s[nf][rr * 2 + 1] = e1 * gy;
            }
            l_run[rr] += ls;
        }

        // ---- wait V, then O += P' V ----
        if (i + 1 < SEQ / 64) cp_wait<1>(); else cp_wait<0>();
        __syncthreads();

#pragma unroll
        for (int kf = 0; kf < 4; kf++) {
            unsigned a0 = pack2(s[2 * kf][0], s[2 * kf][1]);
            unsigned a1 = pack2(s[2 * kf][2], s[2 * kf][3]);
            unsigned a2 = pack2(s[2 * kf + 1][0], s[2 * kf + 1][1]);
            unsigned a3 = pack2(s[2 * kf + 1][2], s[2 * kf + 1][3]);
#pragma unroll
            for (int df2 = 0; df2 < 8; df2++) {
                int row = kf * 16 + (lane & 7) + ((lane >> 3) & 1) * 8;
                int col = df2 * 16 + (lane >> 4) * 8;
                unsigned v0, v1, v2, v3;
                ldsm_x4_t(v0, v1, v2, v3, smem_u32(&Vs[row * APAD + col]));
                mma_bf16(o[2 * df2], a0, a1, a2, a3, v0, v1);
                mma_bf16(o[2 * df2 + 1], a0, a1, a2, a3, v2, v3);
            }
        }
    }

    // final l reduction across the 4 lanes of each row
#pragma unroll
    for (int rr = 0; rr < 2; rr++) {
        l_run[rr] += __shfl_xor_sync(0xffffffffu, l_run[rr], 1);
        l_run[rr] += __shfl_xor_sync(0xffffffffu, l_run[rr], 2);
    }
    float inv0 = 1.f / l_run[0], inv1 = 1.f / l_run[1];
#pragma unroll
    for (int nf = 0; nf < 16; nf++) {
        int d = nf * 8 + tcol;
        __nv_bfloat162 p0, p1;
        p0.x = __float2bfloat16(o[nf][0] * inv0);
        p0.y = __float2bfloat16(o[nf][1] * inv0);
        p1.x = __float2bfloat16(o[nf][2] * inv1);
        p1.y = __float2bfloat16(o[nf][3] * inv1);
        *(__nv_bfloat162*)&g_zb[r0 * EMB + h * HD + d] = p0;
        *(__nv_bfloat162*)&g_zb[(r0 + 8) * EMB + h * HD + d] = p1;
    }
}

// ---------------------------------------------------------------------------
// LayerNorm over last dim (1024). One block per row.
// ---------------------------------------------------------------------------
__global__ __launch_bounds__(256) void ln_kernel(
    const float* __restrict__ gam, const float* __restrict__ bet,
    float* __restrict__ out)
{
    __shared__ float red[2][8];
    int s = blockIdx.x;
    int tid = threadIdx.x;
    const float* row = g_y + s * EMB;

    float4 x = *(const float4*)&row[tid * 4];
    float sum = x.x + x.y + x.z + x.w;
    float sq = x.x * x.x + x.y * x.y + x.z * x.z + x.w * x.w;
#pragma unroll
    for (int w = 16; w; w >>= 1) {
        sum += __shfl_xor_sync(0xffffffffu, sum, w);
        sq  += __shfl_xor_sync(0xffffffffu, sq, w);
    }
    if ((tid & 31) == 0) { red[0][tid >> 5] = sum; red[1][tid >> 5] = sq; }
    __syncthreads();
    if (tid < 32) {
        float s1 = (tid < 8) ? red[0][tid] : 0.f;
        float s2 = (tid < 8) ? red[1][tid] : 0.f;
#pragma unroll
        for (int w = 4; w; w >>= 1) {
            s1 += __shfl_xor_sync(0xffffffffu, s1, w);
            s2 += __shfl_xor_sync(0xffffffffu, s2, w);
        }
        if (tid == 0) { red[0][0] = s1; red[1][0] = s2; }
    }
    __syncthreads();
    float mu = red[0][0] * (1.f / EMB);
    float var = red[1][0] * (1.f / EMB) - mu * mu;
    float inv = rsqrtf(var + 1e-5f);

    float4 gg = *(const float4*)&gam[tid * 4];
    float4 bb = *(const float4*)&bet[tid * 4];
    float4 ov;
    ov.x = (x.x - mu) * inv * gg.x + bb.x;
    ov.y = (x.y - mu) * inv * gg.y + bb.y;
    ov.z = (x.z - mu) * inv * gg.z + bb.z;
    ov.w = (x.w - mu) * inv * gg.w + bb.w;
    *(float4*)&out[s * EMB + tid * 4] = ov;
}

// ---------------------------------------------------------------------------
extern "C" void kernel_launch(void* const* d_in, const int* in_sizes, int n_in,
                              void* d_out, int out_size)
{
    const float* q    = (const float*)d_in[0];
    const float* k    = (const float*)d_in[1];
    const float* v    = (const float*)d_in[2];
    const int*   mask = (const int*)  d_in[3];
    const float* gp   = (const float*)d_in[4];
    const float* Wq   = (const float*)d_in[5];
    const float* bq   = (const float*)d_in[6];
    const float* Wk   = (const float*)d_in[7];
    const float* bk   = (const float*)d_in[8];
    const float* Wv   = (const float*)d_in[9];
    const float* bv   = (const float*)d_in[10];
    const float* Wo   = (const float*)d_in[11];
    const float* bo   = (const float*)d_in[12];
    const float* lng  = (const float*)d_in[13];
    const float* lnb  = (const float*)d_in[14];
    float* out = (float*)d_out;

    cudaFuncSetAttribute(attn_bf16_kernel,
                         cudaFuncAttributeMaxDynamicSharedMemorySize,
                         ATTN_SMEM_BYTES);
    cudaFuncSetAttribute(gemm_qkv_kernel,
                         cudaFuncAttributeMaxDynamicSharedMemorySize,
                         GEMM_SMEM_BYTES);
    cudaFuncSetAttribute(gemm_out_kernel,
                         cudaFuncAttributeMaxDynamicSharedMemorySize,
                         GEMM_SMEM_BYTES);

    conv_in_kernel<<<dim3(SEQ * EMB / (256 * 8), 3), 256>>>(q, k, v);
    conv_w_kernel<<<dim3(EMB * EMB / (256 * 8), 4), 256>>>(Wq, Wk, Wv, Wo);
    prep_gpm_kernel<<<SEQ * SEQ / (256 * 4), 256>>>(mask, gp);

    gemm_qkv_kernel<<<dim3(EMB / 128, SEQ / 128, 3), 256, GEMM_SMEM_BYTES>>>(
        bq, bk, bv);

    attn_bf16_kernel<<<dim3(SEQ / 128, NH), 256, ATTN_SMEM_BYTES>>>();

    gemm_out_kernel<<<dim3(EMB / 128, SEQ / 128), 256, GEMM_SMEM_BYTES>>>(bo, q);

    ln_kernel<<<SEQ, 256>>>(lng, lnb, out);
}

// round 10
// speedup vs baseline: 9.7267x; 1.1095x over previous
#include <cuda_runtime.h>
#include <cuda_bf16.h>
#include <cuda_fp16.h>
#include <math.h>

#define SEQ 4096
#define EMB 1024
#define NH 8
#define HD 128

typedef unsigned int u32;

// Scratch (no allocations allowed): __device__ globals.
__device__ __nv_bfloat16 g_qh[NH * SEQ * HD];
__device__ __nv_bfloat16 g_kh[NH * SEQ * HD];
__device__ __half        g_vh[NH * SEQ * HD];     // V in f16 (PV mma is f16)
__device__ __nv_bfloat16 g_zb[SEQ * EMB];
__device__ __half        g_gpm[SEQ * SEQ];        // mask? gp : -1  (f16)
__device__ __nv_bfloat16 g_xb[3 * SEQ * EMB];     // q,k,v in bf16
__device__ __nv_bfloat16 g_wb[4 * EMB * EMB];     // Wq,Wk,Wv,Wo in bf16
__device__ float g_y[SEQ * EMB];

// ---------------------------------------------------------------------------
// helpers
// ---------------------------------------------------------------------------
__device__ __forceinline__ u32 smem_u32(const void* p) {
    return (u32)__cvta_generic_to_shared(p);
}
__device__ __forceinline__ void cp16(void* dst, const void* src) {
    asm volatile("cp.async.cg.shared.global [%0],[%1],16;"
                 :: "r"(smem_u32(dst)), "l"(src));
}
__device__ __forceinline__ void cp_commit() {
    asm volatile("cp.async.commit_group;");
}
template <int N>
__device__ __forceinline__ void cp_wait() {
    asm volatile("cp.async.wait_group %0;" :: "n"(N));
}
__device__ __forceinline__ void ldsm_x4(u32& r0, u32& r1, u32& r2, u32& r3, u32 addr) {
    asm volatile("ldmatrix.sync.aligned.m8n8.x4.shared.b16 {%0,%1,%2,%3},[%4];"
                 : "=r"(r0), "=r"(r1), "=r"(r2), "=r"(r3) : "r"(addr));
}
__device__ __forceinline__ void ldsm_x4_t(u32& r0, u32& r1, u32& r2, u32& r3, u32 addr) {
    asm volatile("ldmatrix.sync.aligned.m8n8.x4.trans.shared.b16 {%0,%1,%2,%3},[%4];"
                 : "=r"(r0), "=r"(r1), "=r"(r2), "=r"(r3) : "r"(addr));
}
__device__ __forceinline__ void mma_bf16(float* c, u32 a0, u32 a1, u32 a2, u32 a3,
                                         u32 b0, u32 b1) {
    asm volatile(
        "mma.sync.aligned.m16n8k16.row.col.f32.bf16.bf16.f32 "
        "{%0,%1,%2,%3},{%4,%5,%6,%7},{%8,%9},{%0,%1,%2,%3};"
        : "+f"(c[0]), "+f"(c[1]), "+f"(c[2]), "+f"(c[3])
        : "r"(a0), "r"(a1), "r"(a2), "r"(a3), "r"(b0), "r"(b1));
}
__device__ __forceinline__ void mma_f16(float* c, u32 a0, u32 a1, u32 a2, u32 a3,
                                        u32 b0, u32 b1) {
    asm volatile(
        "mma.sync.aligned.m16n8k16.row.col.f32.f16.f16.f32 "
        "{%0,%1,%2,%3},{%4,%5,%6,%7},{%8,%9},{%0,%1,%2,%3};"
        : "+f"(c[0]), "+f"(c[1]), "+f"(c[2]), "+f"(c[3])
        : "r"(a0), "r"(a1), "r"(a2), "r"(a3), "r"(b0), "r"(b1));
}
__device__ __forceinline__ u32 cvt_f16x2(float lo, float hi) {
    u32 r;
    asm("cvt.rn.f16x2.f32 %0,%1,%2;" : "=r"(r) : "f"(hi), "f"(lo));
    return r;
}
__device__ __forceinline__ u32 ex2_f16x2(u32 a) {
    u32 r;
    asm("ex2.approx.f16x2 %0,%1;" : "=r"(r) : "r"(a));
    return r;
}
__device__ __forceinline__ u32 mul_f16x2(u32 a, u32 b) {
    u32 r;
    asm("mul.rn.f16x2 %0,%1,%2;" : "=r"(r) : "r"(a), "r"(b));
    return r;
}

// ---------------------------------------------------------------------------
// prep kernels
// ---------------------------------------------------------------------------
__global__ __launch_bounds__(256) void prep_gpm_kernel(
    const int* __restrict__ mask, const float* __restrict__ gp)
{
    int idx = (blockIdx.x * 256 + threadIdx.x) * 4;
    int4 m = *(const int4*)&mask[idx];
    float4 g = *(const float4*)&gp[idx];
    __half o[4];
    o[0] = __float2half(m.x ? g.x : -1.f);
    o[1] = __float2half(m.y ? g.y : -1.f);
    o[2] = __float2half(m.z ? g.z : -1.f);
    o[3] = __float2half(m.w ? g.w : -1.f);
    *(uint2*)&g_gpm[idx] = *(uint2*)o;
}

__device__ __forceinline__ void conv8(const float* src, __nv_bfloat16* dst, int idx)
{
    float4 a = *(const float4*)&src[idx];
    float4 b = *(const float4*)&src[idx + 4];
    __nv_bfloat162 o[4];
    o[0].x = __float2bfloat16(a.x); o[0].y = __float2bfloat16(a.y);
    o[1].x = __float2bfloat16(a.z); o[1].y = __float2bfloat16(a.w);
    o[2].x = __float2bfloat16(b.x); o[2].y = __float2bfloat16(b.y);
    o[3].x = __float2bfloat16(b.z); o[3].y = __float2bfloat16(b.w);
    *(uint4*)&dst[idx] = *(uint4*)o;
}

__global__ __launch_bounds__(256) void conv_in_kernel(
    const float* __restrict__ q, const float* __restrict__ k,
    const float* __restrict__ v)
{
    int z = blockIdx.y;
    const float* src = (z == 0) ? q : (z == 1) ? k : v;
    conv8(src, g_xb + z * SEQ * EMB, (blockIdx.x * 256 + threadIdx.x) * 8);
}

__global__ __launch_bounds__(256) void conv_w_kernel(
    const float* __restrict__ Wq, const float* __restrict__ Wk,
    const float* __restrict__ Wv, const float* __restrict__ Wo)
{
    int z = blockIdx.y;
    const float* src = (z == 0) ? Wq : (z == 1) ? Wk : (z == 2) ? Wv : Wo;
    conv8(src, g_wb + z * EMB * EMB, (blockIdx.x * 256 + threadIdx.x) * 8);
}

// ---------------------------------------------------------------------------
// bf16 GEMM: C[m,n] = sum_k A[m,k]*W[n,k], cp.async 3-stage pipeline.
// BM=BN=128, BK=32. 128 threads = 4 warps (2m x 2n), warp tile 64x64.
// (A-fragment duplication 2x instead of 4x -> less smem crossbar traffic.)
// ---------------------------------------------------------------------------
#define GP 40                   // bf16 row stride (32+8): 80B, conflict-free ldsm
#define GSTAGE (2 * 128 * GP)   // A+B per stage (elements)
#define GEMM_SMEM_BYTES (3 * GSTAGE * 2)
#define NKSLAB (EMB / 32)       // 32

__device__ __forceinline__ void gemm_stage_load(
    const __nv_bfloat16* A, const __nv_bfloat16* B,
    int m0, int n0, int k0, __nv_bfloat16* st)
{
    const int tid = threadIdx.x;
#pragma unroll
    for (int r = 0; r < 4; r++) {
        int idx = tid + 128 * r;
        int row = idx >> 2, ch = idx & 3;
        cp16(&st[row * GP + ch * 8], &A[(m0 + row) * EMB + k0 + ch * 8]);
        cp16(&st[128 * GP + row * GP + ch * 8], &B[(n0 + row) * EMB + k0 + ch * 8]);
    }
}

__device__ __forceinline__ void gemm_core(
    const __nv_bfloat16* A, const __nv_bfloat16* B,
    int m0, int n0, float c[4][8][4], __nv_bfloat16* gsm)
{
    const int tid = threadIdx.x, lane = tid & 31, w = tid >> 5;
    const int wm = (w >> 1) * 64, wn = (w & 1) * 64;

    gemm_stage_load(A, B, m0, n0, 0, gsm);
    cp_commit();
    gemm_stage_load(A, B, m0, n0, 32, gsm + GSTAGE);
    cp_commit();

    for (int i = 0; i < NKSLAB; i++) {
        if (i + 2 < NKSLAB) {
            gemm_stage_load(A, B, m0, n0, (i + 2) * 32,
                            gsm + ((i + 2) % 3) * GSTAGE);
            cp_commit();
            cp_wait<2>();
        } else if (i + 1 < NKSLAB) {
            cp_wait<1>();
        } else {
            cp_wait<0>();
        }
        __syncthreads();

        __nv_bfloat16* Asm = gsm + (i % 3) * GSTAGE;
        __nv_bfloat16* Bsm = Asm + 128 * GP;
#pragma unroll
        for (int kk = 0; kk < 2; kk++) {
            u32 a[4][4], b[8][2];
#pragma unroll
            for (int mf = 0; mf < 4; mf++) {
                int row = wm + mf * 16 + (lane & 15);
                int col = kk * 16 + (lane >> 4) * 8;
                ldsm_x4(a[mf][0], a[mf][1], a[mf][2], a[mf][3],
                        smem_u32(&Asm[row * GP + col]));
            }
#pragma unroll
            for (int nf2 = 0; nf2 < 4; nf2++) {
                int row = wn + nf2 * 16 + (lane & 7) + ((lane >> 4) << 3);
                int col = kk * 16 + ((lane >> 3) & 1) * 8;
                u32 q0, q1, q2, q3;
                ldsm_x4(q0, q1, q2, q3, smem_u32(&Bsm[row * GP + col]));
                b[nf2 * 2][0] = q0; b[nf2 * 2][1] = q1;
                b[nf2 * 2 + 1][0] = q2; b[nf2 * 2 + 1][1] = q3;
            }
#pragma unroll
            for (int mf = 0; mf < 4; mf++)
#pragma unroll
                for (int nf = 0; nf < 8; nf++)
                    mma_bf16(c[mf][nf], a[mf][0], a[mf][1], a[mf][2], a[mf][3],
                             b[nf][0], b[nf][1]);
        }
        __syncthreads();
    }
}

__global__ __launch_bounds__(128) void gemm_qkv_kernel(
    const float* __restrict__ bq, const float* __restrict__ bk,
    const float* __restrict__ bv)
{
    extern __shared__ __nv_bfloat16 gsm[];
    const int z = blockIdx.z;
    const __nv_bfloat16* A = g_xb + z * SEQ * EMB;
    const __nv_bfloat16* B = g_wb + z * EMB * EMB;
    const float* bias = (z == 0) ? bq : (z == 1) ? bk : bv;

    const int m0 = blockIdx.y * 128, n0 = blockIdx.x * 128;
    const int tid = threadIdx.x, lane = tid & 31, w = tid >> 5;
    const int wm = (w >> 1) * 64, wn = (w & 1) * 64;

    float c[4][8][4];
#pragma unroll
    for (int i = 0; i < 4; i++)
#pragma unroll
        for (int j = 0; j < 8; j++)
#pragma unroll
            for (int e = 0; e < 4; e++) c[i][j][e] = 0.f;

    gemm_core(A, B, m0, n0, c, gsm);

    const int rl = lane >> 2, cb = (lane & 3) * 2;
#pragma unroll
    for (int mf = 0; mf < 4; mf++) {
        int row0 = m0 + wm + mf * 16 + rl;
#pragma unroll
        for (int nf = 0; nf < 8; nf++) {
            int n = n0 + wn + nf * 8 + cb;
            float b0 = bias[n], b1 = bias[n + 1];
            float u0 = c[mf][nf][0] + b0, u1 = c[mf][nf][1] + b1;
            float u2 = c[mf][nf][2] + b0, u3 = c[mf][nf][3] + b1;
            int hh = n >> 7, d = n & 127;
            if (z == 2) {
                __half2 v0 = __floats2half2_rn(u0, u1);
                __half2 v1 = __floats2half2_rn(u2, u3);
                *(__half2*)&g_vh[(hh * SEQ + row0) * HD + d] = v0;
                *(__half2*)&g_vh[(hh * SEQ + row0 + 8) * HD + d] = v1;
            } else {
                __nv_bfloat16* outp = (z == 0) ? g_qh : g_kh;
                __nv_bfloat162 v0, v1;
                v0.x = __float2bfloat16(u0); v0.y = __float2bfloat16(u1);
                v1.x = __float2bfloat16(u2); v1.y = __float2bfloat16(u3);
                *(__nv_bfloat162*)&outp[(hh * SEQ + row0) * HD + d] = v0;
                *(__nv_bfloat162*)&outp[(hh * SEQ + row0 + 8) * HD + d] = v1;
            }
        }
    }
}

__global__ __launch_bounds__(128) void gemm_out_kernel(
    const float* __restrict__ bo, const float* __restrict__ resid)
{
    extern __shared__ __nv_bfloat16 gsm[];
    const int m0 = blockIdx.y * 128, n0 = blockIdx.x * 128;
    const int tid = threadIdx.x, lane = tid & 31, w = tid >> 5;
    const int wm = (w >> 1) * 64, wn = (w & 1) * 64;

    float c[4][8][4];
#pragma unroll
    for (int i = 0; i < 4; i++)
#pragma unroll
        for (int j = 0; j < 8; j++)
#pragma unroll
            for (int e = 0; e < 4; e++) c[i][j][e] = 0.f;

    gemm_core(g_zb, g_wb + 3 * EMB * EMB, m0, n0, c, gsm);

    const int rl = lane >> 2, cb = (lane & 3) * 2;
#pragma unroll
    for (int mf = 0; mf < 4; mf++) {
        int row0 = m0 + wm + mf * 16 + rl;
#pragma unroll
        for (int nf = 0; nf < 8; nf++) {
            int n = n0 + wn + nf * 8 + cb;
            float b0 = bo[n], b1 = bo[n + 1];
            float2 r0v = *(const float2*)&resid[row0 * EMB + n];
            float2 r1v = *(const float2*)&resid[(row0 + 8) * EMB + n];
            float2 y0 = {c[mf][nf][0] + b0 + r0v.x, c[mf][nf][1] + b1 + r0v.y};
            float2 y1 = {c[mf][nf][2] + b0 + r1v.x, c[mf][nf][3] + b1 + r1v.y};
            *(float2*)&g_y[row0 * EMB + n] = y0;
            *(float2*)&g_y[(row0 + 8) * EMB + n] = y1;
        }
    }
}

// ---------------------------------------------------------------------------
// Flash attention. S: bf16 mma. Softmax: vector f16x2 EX2 (half the MUFU).
// PV: f16 mma (P*gpm fragments directly from mul.f16x2; V stored f16).
// 256 threads (8 warps), q-tile 128 rows, kv tile 64.
// ---------------------------------------------------------------------------
#define APAD 136
#define GPMPAD 72
#define KV_ELEMS (64 * APAD)
#define G_ELEMS (128 * GPMPAD)
// layout (16-bit elems): K0 | K1 | V | G0 | G1
#define OFF_K(st) ((st) * KV_ELEMS)
#define OFF_V     (2 * KV_ELEMS)
#define OFF_G(st) (3 * KV_ELEMS + (st) * G_ELEMS)
#define ATTN_SMEM_BYTES ((3 * KV_ELEMS + 2 * G_ELEMS) * 2)

__global__ __launch_bounds__(256, 2) void attn_bf16_kernel()
{
    extern __shared__ __nv_bfloat16 sm_[];
    const int h = blockIdx.y, s0 = blockIdx.x * 128;
    const int tid = threadIdx.x, lane = tid & 31, w = tid >> 5;
    const float SC2 = 0.12751744f;   // log2(e)/sqrt(128)
    const float M2 = 11.541560f;     // 8*log2(e)

    const __nv_bfloat16* Qg = g_qh + h * SEQ * HD;
    const __nv_bfloat16* Kg = g_kh + h * SEQ * HD;
    const __half* Vg = g_vh + h * SEQ * HD;

    // ---- prefetch tile 0 of K (64x128) and gpm (128x64) ----
#pragma unroll
    for (int r = 0; r < 4; r++) {
        int idx = tid + 256 * r;
        int row = idx >> 4, ch = idx & 15;
        cp16(&sm_[OFF_K(0) + row * APAD + ch * 8], &Kg[row * HD + ch * 8]);
    }
#pragma unroll
    for (int r = 0; r < 4; r++) {
        int idx = tid + 256 * r;
        int row = idx >> 3, ch = idx & 7;
        cp16(&sm_[OFF_G(0) + row * GPMPAD + ch * 8],
             &g_gpm[(s0 + row) * SEQ + ch * 8]);
    }
    cp_commit();

    // ---- load Q fragments directly from global ----
    u32 aq[8][4];
    {
        int row = s0 + w * 16 + (lane >> 2);
        int col = (lane & 3) * 2;
#pragma unroll
        for (int kf = 0; kf < 8; kf++) {
            aq[kf][0] = *(const u32*)&Qg[row * HD + kf * 16 + col];
            aq[kf][1] = *(const u32*)&Qg[(row + 8) * HD + kf * 16 + col];
            aq[kf][2] = *(const u32*)&Qg[row * HD + kf * 16 + col + 8];
            aq[kf][3] = *(const u32*)&Qg[(row + 8) * HD + kf * 16 + col + 8];
        }
    }

    float o[16][4];
    float l_run[2] = {0.f, 0.f};
#pragma unroll
    for (int nf = 0; nf < 16; nf++)
#pragma unroll
        for (int e = 0; e < 4; e++) o[nf][e] = 0.f;

    const int rloc = w * 16 + (lane >> 2);   // local q row
    const int r0 = s0 + rloc;
    const int tcol = (lane & 3) * 2;

    for (int i = 0; i < SEQ / 64; i++) {
        cp_wait<0>();
        __syncthreads();

        const int st = i & 1;
        const __nv_bfloat16* Ks = sm_ + OFF_K(st);
        const __nv_bfloat16* Vs = sm_ + OFF_V;
        const __half* Gs = (const __half*)(sm_ + OFF_G(st));

        // issue V_i
#pragma unroll
        for (int r = 0; r < 4; r++) {
            int idx = tid + 256 * r;
            int row = idx >> 4, ch = idx & 15;
            cp16(&sm_[OFF_V + row * APAD + ch * 8],
                 &Vg[(i * 64 + row) * HD + ch * 8]);
        }
        cp_commit();

        // issue K_{i+1}, G_{i+1}
        if (i + 1 < SEQ / 64) {
            const int t1 = (i + 1) * 64;
#pragma unroll
            for (int r = 0; r < 4; r++) {
                int idx = tid + 256 * r;
                int row = idx >> 4, ch = idx & 15;
                cp16(&sm_[OFF_K(st ^ 1) + row * APAD + ch * 8],
                     &Kg[(t1 + row) * HD + ch * 8]);
            }
#pragma unroll
            for (int r = 0; r < 4; r++) {
                int idx = tid + 256 * r;
                int row = idx >> 3, ch = idx & 7;
                cp16(&sm_[OFF_G(st ^ 1) + row * GPMPAD + ch * 8],
                     &g_gpm[(s0 + row) * SEQ + t1 + ch * 8]);
            }
            cp_commit();
        }

        // ---- S = Q K^T ----
        float s[8][4];
#pragma unroll
        for (int nf = 0; nf < 8; nf++)
#pragma unroll
            for (int e = 0; e < 4; e++) s[nf][e] = 0.f;

#pragma unroll
        for (int kf = 0; kf < 8; kf++) {
            u32 b[8][2];
#pragma unroll
            for (int nf2 = 0; nf2 < 4; nf2++) {
                int row = nf2 * 16 + (lane & 7) + ((lane >> 4) << 3);
                int col = kf * 16 + ((lane >> 3) & 1) * 8;
                u32 q0, q1, q2, q3;
                ldsm_x4(q0, q1, q2, q3, smem_u32(&Ks[row * APAD + col]));
                b[nf2 * 2][0] = q0; b[nf2 * 2][1] = q1;
                b[nf2 * 2 + 1][0] = q2; b[nf2 * 2 + 1][1] = q3;
            }
#pragma unroll
            for (int nf = 0; nf < 8; nf++)
                mma_bf16(s[nf], aq[kf][0], aq[kf][1], aq[kf][2], aq[kf][3],
                         b[nf][0], b[nf][1]);
        }

        // ---- fixed-max softmax (vector f16x2 EX2) + gpm/mask fold ----
        u32 pga[8][2];
#pragma unroll
        for (int rr = 0; rr < 2; rr++) {
            const __half* grow = Gs + (rloc + rr * 8) * GPMPAD + tcol;
            float ls = 0.f;
#pragma unroll
            for (int nf = 0; nf < 8; nf++) {
                u32 gbits = *(const u32*)&grow[nf * 8];
                __half2 gh = *(__half2*)&gbits;
                float gx = __half2float(gh.x);
                float gy = __half2float(gh.y);
                float a0 = fmaf(s[nf][rr * 2], SC2, -M2);
                float a1 = fmaf(s[nf][rr * 2 + 1], SC2, -M2);
                a0 = (gx >= 0.f) ? a0 : -1e4f;
                a1 = (gy >= 0.f) ? a1 : -1e4f;
                u32 p2 = ex2_f16x2(cvt_f16x2(a0, a1));
                __half2 ph = *(__half2*)&p2;
                ls += __half2float(ph.x) + __half2float(ph.y);
                pga[nf][rr] = mul_f16x2(p2, gbits);
            }
            l_run[rr] += ls;
        }

        // ---- wait V, then O += P' V (f16 mma) ----
        if (i + 1 < SEQ / 64) cp_wait<1>(); else cp_wait<0>();
        __syncthreads();

#pragma unroll
        for (int kf = 0; kf < 4; kf++) {
            u32 a0 = pga[2 * kf][0];
            u32 a1 = pga[2 * kf][1];
            u32 a2 = pga[2 * kf + 1][0];
            u32 a3 = pga[2 * kf + 1][1];
#pragma unroll
            for (int df2 = 0; df2 < 8; df2++) {
                int row = kf * 16 + (lane & 7) + ((lane >> 3) & 1) * 8;
                int col = df2 * 16 + (lane >> 4) * 8;
                u32 v0, v1, v2, v3;
                ldsm_x4_t(v0, v1, v2, v3, smem_u32(&Vs[row * APAD + col]));
                mma_f16(o[2 * df2], a0, a1, a2, a3, v0, v1);
                mma_f16(o[2 * df2 + 1], a0, a1, a2, a3, v2, v3);
            }
        }
    }

    // final l reduction across the 4 lanes of each row
#pragma unroll
    for (int rr = 0; rr < 2; rr++) {
        l_run[rr] += __shfl_xor_sync(0xffffffffu, l_run[rr], 1);
        l_run[rr] += __shfl_xor_sync(0xffffffffu, l_run[rr], 2);
    }
    float inv0 = 1.f / l_run[0], inv1 = 1.f / l_run[1];
#pragma unroll
    for (int nf = 0; nf < 16; nf++) {
        int d = nf * 8 + tcol;
        __nv_bfloat162 p0, p1;
        p0.x = __float2bfloat16(o[nf][0] * inv0);
        p0.y = __float2bfloat16(o[nf][1] * inv0);
        p1.x = __float2bfloat16(o[nf][2] * inv1);
        p1.y = __float2bfloat16(o[nf][3] * inv1);
        *(__nv_bfloat162*)&g_zb[r0 * EMB + h * HD + d] = p0;
        *(__nv_bfloat162*)&g_zb[(r0 + 8) * EMB + h * HD + d] = p1;
    }
}

// ---------------------------------------------------------------------------
// LayerNorm over last dim (1024). One block per row.
// ---------------------------------------------------------------------------
__global__ __launch_bounds__(256) void ln_kernel(
    const float* __restrict__ gam, const float* __restrict__ bet,
    float* __restrict__ out)
{
    __shared__ float red[2][8];
    int s = blockIdx.x;
    int tid = threadIdx.x;
    const float* row = g_y + s * EMB;

    float4 x = *(const float4*)&row[tid * 4];
    float sum = x.x + x.y + x.z + x.w;
    float sq = x.x * x.x + x.y * x.y + x.z * x.z + x.w * x.w;
#pragma unroll
    for (int w = 16; w; w >>= 1) {
        sum += __shfl_xor_sync(0xffffffffu, sum, w);
        sq  += __shfl_xor_sync(0xffffffffu, sq, w);
    }
    if ((tid & 31) == 0) { red[0][tid >> 5] = sum; red[1][tid >> 5] = sq; }
    __syncthreads();
    if (tid < 32) {
        float s1 = (tid < 8) ? red[0][tid] : 0.f;
        float s2 = (tid < 8) ? red[1][tid] : 0.f;
#pragma unroll
        for (int w = 4; w; w >>= 1) {
            s1 += __shfl_xor_sync(0xffffffffu, s1, w);
            s2 += __shfl_xor_sync(0xffffffffu, s2, w);
        }
        if (tid == 0) { red[0][0] = s1; red[1][0] = s2; }
    }
    __syncthreads();
    float mu = red[0][0] * (1.f / EMB);
    float var = red[1][0] * (1.f / EMB) - mu * mu;
    float inv = rsqrtf(var + 1e-5f);

    float4 gg = *(const float4*)&gam[tid * 4];
    float4 bb = *(const float4*)&bet[tid * 4];
    float4 ov;
    ov.x = (x.x - mu) * inv * gg.x + bb.x;
    ov.y = (x.y - mu) * inv * gg.y + bb.y;
    ov.z = (x.z - mu) * inv * gg.z + bb.z;
    ov.w = (x.w - mu) * inv * gg.w + bb.w;
    *(float4*)&out[s * EMB + tid * 4] = ov;
}

// ---------------------------------------------------------------------------
extern "C" void kernel_launch(void* const* d_in, const int* in_sizes, int n_in,
                              void* d_out, int out_size)
{
    const float* q    = (const float*)d_in[0];
    const float* k    = (const float*)d_in[1];
    const float* v    = (const float*)d_in[2];
    const int*   mask = (const int*)  d_in[3];
    const float* gp   = (const float*)d_in[4];
    const float* Wq   = (const float*)d_in[5];
    const float* bq   = (const float*)d_in[6];
    const float* Wk   = (const float*)d_in[7];
    const float* bk   = (const float*)d_in[8];
    const float* Wv   = (const float*)d_in[9];
    const float* bv   = (const float*)d_in[10];
    const float* Wo   = (const float*)d_in[11];
    const float* bo   = (const float*)d_in[12];
    const float* lng  = (const float*)d_in[13];
    const float* lnb  = (const float*)d_in[14];
    float* out = (float*)d_out;

    cudaFuncSetAttribute(attn_bf16_kernel,
                         cudaFuncAttributeMaxDynamicSharedMemorySize,
                         ATTN_SMEM_BYTES);
    cudaFuncSetAttribute(gemm_qkv_kernel,
                         cudaFuncAttributeMaxDynamicSharedMemorySize,
                         GEMM_SMEM_BYTES);
    cudaFuncSetAttribute(gemm_out_kernel,
                         cudaFuncAttributeMaxDynamicSharedMemorySize,
                         GEMM_SMEM_BYTES);

    conv_in_kernel<<<dim3(SEQ * EMB / (256 * 8), 3), 256>>>(q, k, v);
    conv_w_kernel<<<dim3(EMB * EMB / (256 * 8), 4), 256>>>(Wq, Wk, Wv, Wo);
    prep_gpm_kernel<<<SEQ * SEQ / (256 * 4), 256>>>(mask, gp);

    gemm_qkv_kernel<<<dim3(EMB / 128, SEQ / 128, 3), 128, GEMM_SMEM_BYTES>>>(
        bq, bk, bv);

    attn_bf16_kernel<<<dim3(SEQ / 128, NH), 256, ATTN_SMEM_BYTES>>>();

    gemm_out_kernel<<<dim3(EMB / 128, SEQ / 128), 128, GEMM_SMEM_BYTES>>>(bo, q);

    ln_kernel<<<SEQ, 256>>>(lng, lnb, out);
}